// round 14
// baseline (speedup 1.0000x reference)
#include <cuda_runtime.h>
#include <cuda_fp16.h>
#include <cstdint>
#include <math.h>

#define D_MODEL   1024
#define NUM_HEADS 16
#define DK        64
#define BATCH     2
#define SEQ       2048
#define M_TOTAL   (BATCH * SEQ)          // 4096
#define HEADS_TOT (BATCH * NUM_HEADS)    // 32

// log2(e)/sqrt(64) folded into Q
#define QSCALE 0.18033688011112042f

// ---------------- scratch (no cudaMalloc allowed) ----------------
__device__ __half g_Xh[(size_t)M_TOTAL * D_MODEL];
__device__ __half g_Xl[(size_t)M_TOTAL * D_MODEL];
__device__ __half g_Wh[4][(size_t)D_MODEL * D_MODEL];
__device__ __half g_Wl[4][(size_t)D_MODEL * D_MODEL];
__device__ __half g_Qh[(size_t)HEADS_TOT * SEQ * DK];
__device__ __half g_Ql[(size_t)HEADS_TOT * SEQ * DK];
__device__ __half g_Kh[(size_t)HEADS_TOT * SEQ * DK];
__device__ __half g_Kl[(size_t)HEADS_TOT * SEQ * DK];
__device__ __half g_Vth[(size_t)HEADS_TOT * DK * SEQ];  // fp16-only V (transposed)
__device__ __half g_Ah[(size_t)HEADS_TOT * SEQ * DK];   // attn out, fp16 only

// ---------------- ptx helpers ----------------
__device__ __forceinline__ uint32_t smem_u32(const void* p) {
    uint32_t a;
    asm("{ .reg .u64 t; cvta.to.shared.u64 t, %1; cvt.u32.u64 %0, t; }" : "=r"(a) : "l"(p));
    return a;
}
__device__ __forceinline__ void cp16(uint32_t dst, const void* src) {
    asm volatile("cp.async.cg.shared.global [%0], [%1], 16;" :: "r"(dst), "l"(src));
}
#define CP_COMMIT() asm volatile("cp.async.commit_group;" ::: "memory")
#define CP_WAIT(n)  asm volatile("cp.async.wait_group %0;" :: "n"(n) : "memory")

__device__ __forceinline__ void ldsm4(uint32_t& r0, uint32_t& r1, uint32_t& r2, uint32_t& r3,
                                      uint32_t addr) {
    asm volatile("ldmatrix.sync.aligned.m8n8.x4.shared.b16 {%0,%1,%2,%3}, [%4];"
                 : "=r"(r0), "=r"(r1), "=r"(r2), "=r"(r3) : "r"(addr));
}
__device__ __forceinline__ void mma16816(float* d, const uint32_t* a, const uint32_t* b) {
    asm volatile("mma.sync.aligned.m16n8k16.row.col.f32.f16.f16.f32 "
        "{%0,%1,%2,%3}, {%4,%5,%6,%7}, {%8,%9}, {%0,%1,%2,%3};"
        : "+f"(d[0]), "+f"(d[1]), "+f"(d[2]), "+f"(d[3])
        : "r"(a[0]), "r"(a[1]), "r"(a[2]), "r"(a[3]), "r"(b[0]), "r"(b[1]));
}
__device__ __forceinline__ void splith2(float x, float y, uint32_t& hi, uint32_t& lo) {
    __half2 H = __floats2half2_rn(x, y);
    float rx = x - __half2float(__low2half(H));
    float ry = y - __half2float(__high2half(H));
    __half2 L = __floats2half2_rn(rx, ry);
    hi = *(uint32_t*)&H;
    lo = *(uint32_t*)&L;
}
__device__ __forceinline__ uint32_t packh2(float x, float y) {
    __half2 H = __floats2half2_rn(x, y);
    return *(uint32_t*)&H;
}
__device__ __forceinline__ float ex2f(float x) {
    float r; asm("ex2.approx.f32 %0, %1;" : "=f"(r) : "f"(x)); return r;
}
__device__ __forceinline__ float rmax4(float v) {
    v = fmaxf(v, __shfl_xor_sync(0xffffffffu, v, 1));
    v = fmaxf(v, __shfl_xor_sync(0xffffffffu, v, 2));
    return v;
}
__device__ __forceinline__ float rsum4(float v) {
    v += __shfl_xor_sync(0xffffffffu, v, 1);
    v += __shfl_xor_sync(0xffffffffu, v, 2);
    return v;
}

// =================================================================
// fused fp32 -> (hi, lo) fp16 split for X + 4 weights (one launch)
// (lo skipped for Wv/Wo — value path is fp16-only now)
// =================================================================
__global__ __launch_bounds__(256)
void cvt_all(const float* __restrict__ X,  const float* __restrict__ Wq,
             const float* __restrict__ Wk, const float* __restrict__ Wv,
             const float* __restrict__ Wo)
{
    const int bid = blockIdx.x;
    const float* src;
    __half *hi, *lo;
    bool wlo = true;
    int i;
    if (bid < 4096) {
        src = X; hi = g_Xh; lo = g_Xl;
        i = bid * 256 + threadIdx.x;
    } else {
        const int seg = (bid - 4096) >> 10;
        i = ((bid - 4096) & 1023) * 256 + threadIdx.x;
        src = seg == 0 ? Wq : seg == 1 ? Wk : seg == 2 ? Wv : Wo;
        hi = g_Wh[seg]; lo = g_Wl[seg];
        wlo = (seg < 2);
    }
    float4 v = ((const float4*)src)[i];
    uint32_t h0, l0, h1, l1;
    splith2(v.x, v.y, h0, l0);
    splith2(v.z, v.w, h1, l1);
    ((uint2*)hi)[i] = make_uint2(h0, h1);
    if (wlo) ((uint2*)lo)[i] = make_uint2(l0, l1);
}

// =================================================================
// split-fp16 HMMA GEMM: block 128x128, BK=32, 8 warps (4x2), warp 32x64.
// terms = 3 (hh+hl+lh), 2 (hh+hl), or 1 (hh). f32 acc.
// =================================================================
#define BM 128
#define BN 128
#define BK 32
#define SSTR   40
#define TILE_B (BM * SSTR * 2)
#define STAGE_B (4 * TILE_B)
#define GEMM_SMEM (2 * STAGE_B)          // 81920 B

template<bool QKV>
__device__ __forceinline__ void issue_copies(uint32_t stage_sb, int tid, int m0, int n0, int kc,
                                             const __half* __restrict__ Wh,
                                             const __half* __restrict__ Wl,
                                             bool copy_alo, bool copy_blo)
{
    const int k0 = kc * BK;
#pragma unroll
    for (int o = 0; o < 8; o++) {
        const int e    = o * 256 + tid;
        const int tile = e >> 9;
        if (tile == 1 && !copy_alo) continue;
        if (tile == 3 && !copy_blo) continue;
        const int idx  = e & 511;
        const int r = idx >> 2, c = idx & 3;
        const uint32_t dst = stage_sb + tile * TILE_B + r * (SSTR * 2) + c * 16;
        const __half* src;
        if (tile < 2) {
            size_t ai;
            if (QKV) {
                ai = (size_t)(m0 + r) * D_MODEL + k0 + c * 8;
            } else {
                const int m = m0 + r;
                ai = (((size_t)(m >> 11) * NUM_HEADS + (k0 >> 6)) * SEQ + (m & (SEQ - 1))) * DK
                     + (k0 & 63) + c * 8;
            }
            src = (tile == 0 ? (QKV ? g_Xh : g_Ah) : g_Xl) + ai;
        } else {
            const size_t bi = (size_t)(n0 + r) * D_MODEL + k0 + c * 8;
            src = (tile == 2 ? Wh : Wl) + bi;
        }
        cp16(dst, src);
    }
}

__device__ __forceinline__ void mma_stage(uint32_t Abase, int lane, int wm, int wn,
                                          float acc[2][8][4], int terms)
{
#pragma unroll
    for (int h = 0; h < 2; h++) {
        uint32_t ah[2][4], al[2][4];
#pragma unroll
        for (int mt = 0; mt < 2; mt++) {
            const uint32_t addr = Abase
                + (uint32_t)(wm * 32 + mt * 16 + (lane & 15)) * (SSTR * 2)
                + h * 32 + ((lane >> 4) << 4);
            ldsm4(ah[mt][0], ah[mt][1], ah[mt][2], ah[mt][3], addr);
            if (terms >= 3)
                ldsm4(al[mt][0], al[mt][1], al[mt][2], al[mt][3], addr + TILE_B);
        }
        uint32_t bh[4][4], bl[4][4];
#pragma unroll
        for (int nt = 0; nt < 4; nt++) {
            const uint32_t addr = Abase + 2 * TILE_B
                + (uint32_t)(wn * 64 + nt * 16 + (lane & 7) + ((lane >> 4) << 3)) * (SSTR * 2)
                + h * 32 + (((lane >> 3) & 1) << 4);
            ldsm4(bh[nt][0], bh[nt][1], bh[nt][2], bh[nt][3], addr);
            if (terms >= 2)
                ldsm4(bl[nt][0], bl[nt][1], bl[nt][2], bl[nt][3], addr + TILE_B);
        }
#pragma unroll
        for (int mt = 0; mt < 2; mt++)
#pragma unroll
            for (int nt = 0; nt < 4; nt++) {
                mma16816(acc[mt][2 * nt],     ah[mt], &bh[nt][0]);
                mma16816(acc[mt][2 * nt + 1], ah[mt], &bh[nt][2]);
            }
        if (terms >= 2) {
#pragma unroll
            for (int mt = 0; mt < 2; mt++)
#pragma unroll
                for (int nt = 0; nt < 4; nt++) {
                    mma16816(acc[mt][2 * nt],     ah[mt], &bl[nt][0]);
                    mma16816(acc[mt][2 * nt + 1], ah[mt], &bl[nt][2]);
                }
        }
        if (terms >= 3) {
#pragma unroll
            for (int mt = 0; mt < 2; mt++)
#pragma unroll
                for (int nt = 0; nt < 4; nt++) {
                    mma16816(acc[mt][2 * nt],     al[mt], &bh[nt][0]);
                    mma16816(acc[mt][2 * nt + 1], al[mt], &bh[nt][2]);
                }
        }
    }
}

template<bool QKV>
__device__ __forceinline__ void gemm_body(float acc[2][8][4], uint32_t sb, int tid,
                                          int m0, int n0, int terms,
                                          const __half* __restrict__ Wh,
                                          const __half* __restrict__ Wl)
{
    const int lane = tid & 31, wid = tid >> 5;
    const int wm = wid >> 1, wn = wid & 1;
    const int NKC = D_MODEL / BK;
    const bool ca = (terms >= 3), cb = (terms >= 2);

    issue_copies<QKV>(sb, tid, m0, n0, 0, Wh, Wl, ca, cb);
    CP_COMMIT();
    for (int kc = 0; kc < NKC; kc++) {
        CP_WAIT(0);
        __syncthreads();
        if (kc + 1 < NKC) {
            issue_copies<QKV>(sb + ((kc + 1) & 1) * STAGE_B, tid, m0, n0, kc + 1, Wh, Wl, ca, cb);
            CP_COMMIT();
        }
        mma_stage(sb + (kc & 1) * STAGE_B, lane, wm, wn, acc, terms);
    }
}

__global__ __launch_bounds__(256, 2)
void gemm_qkv_mma()
{
    extern __shared__ char smem[];
    const uint32_t sb = smem_u32(smem);
    const int tid = threadIdx.x;
    const int z  = blockIdx.z;
    const int m0 = blockIdx.y * BM, n0 = blockIdx.x * BN;

    float acc[2][8][4];
#pragma unroll
    for (int a = 0; a < 2; a++)
#pragma unroll
        for (int b = 0; b < 8; b++)
#pragma unroll
            for (int c = 0; c < 4; c++) acc[a][b][c] = 0.f;

    // Q,K: 3-term (score path). V: 1-term (value path, fp16 x fp16).
    gemm_body<true>(acc, sb, tid, m0, n0, (z < 2) ? 3 : 1, g_Wh[z], g_Wl[z]);

    const float scale = (z == 0) ? QSCALE : 1.0f;
    const int lane = tid & 31, wid = tid >> 5;
    const int wm = wid >> 1, wn = wid & 1;
    const int h = ((n0 + wn * 64) >> 6);
#pragma unroll
    for (int mt = 0; mt < 2; mt++)
#pragma unroll
        for (int rr = 0; rr < 2; rr++) {
            const int m = m0 + wm * 32 + mt * 16 + rr * 8 + (lane >> 2);
            const int b = m >> 11, s = m & (SEQ - 1);
            const int head = b * NUM_HEADS + h;
#pragma unroll
            for (int j = 0; j < 8; j++) {
                const int t = j * 8 + 2 * (lane & 3);
                const float x = acc[mt][j][2 * rr] * scale;
                const float y = acc[mt][j][2 * rr + 1] * scale;
                if (z == 2) {
                    const size_t base = ((size_t)head * DK + t) * SEQ + s;
                    g_Vth[base]       = __float2half_rn(x);
                    g_Vth[base + SEQ] = __float2half_rn(y);
                } else {
                    uint32_t hi, lo;
                    splith2(x, y, hi, lo);
                    const size_t base = ((size_t)head * SEQ + s) * DK + t;
                    if (z == 0) {
                        *(uint32_t*)&g_Qh[base] = hi;
                        *(uint32_t*)&g_Ql[base] = lo;
                    } else {
                        *(uint32_t*)&g_Kh[base] = hi;
                        *(uint32_t*)&g_Kl[base] = lo;
                    }
                }
            }
        }
}

__global__ __launch_bounds__(256, 2)
void gemm_out_mma(float* __restrict__ C)
{
    extern __shared__ char smem[];
    const uint32_t sb = smem_u32(smem);
    const int tid = threadIdx.x;
    const int m0 = blockIdx.y * BM, n0 = blockIdx.x * BN;

    float acc[2][8][4];
#pragma unroll
    for (int a = 0; a < 2; a++)
#pragma unroll
        for (int b = 0; b < 8; b++)
#pragma unroll
            for (int c = 0; c < 4; c++) acc[a][b][c] = 0.f;

    // value path: 1-term (A = attn out fp16, B = Wo fp16)
    gemm_body<false>(acc, sb, tid, m0, n0, 1, g_Wh[3], g_Wl[3]);

    const int lane = tid & 31, wid = tid >> 5;
    const int wm = wid >> 1, wn = wid & 1;
#pragma unroll
    for (int mt = 0; mt < 2; mt++)
#pragma unroll
        for (int rr = 0; rr < 2; rr++) {
            const int m = m0 + wm * 32 + mt * 16 + rr * 8 + (lane >> 2);
            float* dst = &C[(size_t)m * D_MODEL + n0 + wn * 64];
#pragma unroll
            for (int j = 0; j < 8; j++) {
                const int t = j * 8 + 2 * (lane & 3);
                float2 v = rr == 0 ? make_float2(acc[mt][j][0], acc[mt][j][1])
                                   : make_float2(acc[mt][j][2], acc[mt][j][3]);
                *(float2*)&dst[t] = v;
            }
        }
}

// =================================================================
// Flash attention: QK 3-term (22-bit scores), PV 1-term (fp16 x fp16).
// Stage = {Kh, Kl, Vth} = 3 tiles. Double-buffered, causal warp skip.
// =================================================================
#define AT_SSTR  72
#define AT_ROWB  (AT_SSTR * 2)           // 144
#define AT_TILEB (64 * AT_ROWB)          // 9216
#define AT_STAGE (3 * AT_TILEB)          // 27648
#define ATTN_SMEM (2 * AT_STAGE)         // 55296

__device__ __forceinline__ void attn_issue(uint32_t stage_sb, int tid, int head, int k0)
{
#pragma unroll
    for (int i = 0; i < 6; i++) {
        const int e = i * 256 + tid;                 // 0..1535
        const int arr = e >> 9, idx = e & 511;
        const int row = idx >> 3, c = idx & 7;
        const uint32_t dst = stage_sb + arr * AT_TILEB + row * AT_ROWB + c * 16;
        const __half* src;
        if (arr == 0)      src = g_Kh  + ((size_t)head * SEQ + k0 + row) * DK + c * 8;
        else if (arr == 1) src = g_Kl  + ((size_t)head * SEQ + k0 + row) * DK + c * 8;
        else               src = g_Vth + ((size_t)head * DK + row) * SEQ + k0 + c * 8;
        cp16(dst, src);
    }
}

__global__ __launch_bounds__(256)
void attn_mma()
{
    extern __shared__ char smem[];
    const uint32_t sb = smem_u32(smem);
    const int tid = threadIdx.x, lane = tid & 31, w = tid >> 5;
    const int head = blockIdx.y;
    const int q0 = (int)(gridDim.x - 1 - blockIdx.x) * 128;
    const int qwb = q0 + w * 16;

    // ---- stage Q (hi = tiles 0-1, lo = tiles 2-3 of smem area) ----
    {
        const __half* Qh = g_Qh + ((size_t)head * SEQ + q0) * DK;
        const __half* Ql = g_Ql + ((size_t)head * SEQ + q0) * DK;
#pragma unroll
        for (int i = 0; i < 8; i++) {
            const int e = i * 256 + tid;
            const int half_ = e >> 10;
            const int idx = e & 1023;
            const int row = idx >> 3, c = idx & 7;
            const uint32_t dst = sb + half_ * (2 * AT_TILEB) + row * AT_ROWB + c * 16;
            const __half* src = (half_ ? Ql : Qh) + (size_t)row * DK + c * 8;
            cp16(dst, src);
        }
        CP_COMMIT(); CP_WAIT(0);
        __syncthreads();
    }
    uint32_t qh[4][4], ql[4][4];
#pragma unroll
    for (int kc = 0; kc < 4; kc++) {
        const uint32_t a = sb + (uint32_t)(w * 16 + (lane & 15)) * AT_ROWB
                         + kc * 32 + ((lane >> 4) << 4);
        ldsm4(qh[kc][0], qh[kc][1], qh[kc][2], qh[kc][3], a);
        ldsm4(ql[kc][0], ql[kc][1], ql[kc][2], ql[kc][3], a + 2 * AT_TILEB);
    }
    __syncthreads();

    float o[8][4];
#pragma unroll
    for (int nt = 0; nt < 8; nt++)
#pragma unroll
        for (int r = 0; r < 4; r++) o[nt][r] = 0.f;
    float mrow0 = -1e30f, mrow1 = -1e30f, lrow0 = 0.f, lrow1 = 0.f;

    const int ktiles = (q0 >> 6) + 2;

    attn_issue(sb, tid, head, 0);
    CP_COMMIT();

    for (int t = 0; t < ktiles; t++) {
        const int k0 = t * 64;
        CP_WAIT(0);
        __syncthreads();
        if (t + 1 < ktiles) {
            attn_issue(sb + ((t + 1) & 1) * AT_STAGE, tid, head, k0 + 64);
            CP_COMMIT();
        }
        if (k0 > qwb + 15) continue;           // fully-masked tile for this warp
        const uint32_t stg = sb + (t & 1) * AT_STAGE;

        // ---- QK^T, 3-term (score path) ----
        float sc[8][4];
#pragma unroll
        for (int nt = 0; nt < 8; nt++)
#pragma unroll
            for (int r = 0; r < 4; r++) sc[nt][r] = 0.f;
#pragma unroll
        for (int kc = 0; kc < 4; kc++)
#pragma unroll
            for (int gp = 0; gp < 2; gp++) {
                uint32_t kh[2][4], kl[2][4];
#pragma unroll
                for (int gi = 0; gi < 2; gi++) {
                    const int g = gp * 2 + gi;
                    const uint32_t ad = stg
                        + (uint32_t)(g * 16 + (lane & 7) + ((lane >> 4) << 3)) * AT_ROWB
                        + kc * 32 + (((lane >> 3) & 1) << 4);
                    ldsm4(kh[gi][0], kh[gi][1], kh[gi][2], kh[gi][3], ad);
                    ldsm4(kl[gi][0], kl[gi][1], kl[gi][2], kl[gi][3], ad + AT_TILEB);
                }
#pragma unroll
                for (int gi = 0; gi < 2; gi++) {
                    const int g = gp * 2 + gi;
                    mma16816(sc[2 * g],     qh[kc], &kh[gi][0]);
                    mma16816(sc[2 * g + 1], qh[kc], &kh[gi][2]);
                }
#pragma unroll
                for (int gi = 0; gi < 2; gi++) {
                    const int g = gp * 2 + gi;
                    mma16816(sc[2 * g],     qh[kc], &kl[gi][0]);
                    mma16816(sc[2 * g + 1], qh[kc], &kl[gi][2]);
                }
#pragma unroll
                for (int gi = 0; gi < 2; gi++) {
                    const int g = gp * 2 + gi;
                    mma16816(sc[2 * g],     ql[kc], &kh[gi][0]);
                    mma16816(sc[2 * g + 1], ql[kc], &kh[gi][2]);
                }
            }

        // ---- causal mask (diagonal tiles only) ----
        if (k0 + 63 > qwb) {
            const int r0 = qwb + (lane >> 2);
            const int kb = k0 + 2 * (lane & 3);
#pragma unroll
            for (int nt = 0; nt < 8; nt++) {
                const int kk = kb + nt * 8;
                if (kk     > r0)     sc[nt][0] = -1e30f;
                if (kk + 1 > r0)     sc[nt][1] = -1e30f;
                if (kk     > r0 + 8) sc[nt][2] = -1e30f;
                if (kk + 1 > r0 + 8) sc[nt][3] = -1e30f;
            }
        }

        // ---- online softmax (base 2) ----
        float mx0 = sc[0][0], mx1 = sc[0][2];
#pragma unroll
        for (int nt = 0; nt < 8; nt++) {
            mx0 = fmaxf(mx0, fmaxf(sc[nt][0], sc[nt][1]));
            mx1 = fmaxf(mx1, fmaxf(sc[nt][2], sc[nt][3]));
        }
        mx0 = rmax4(mx0); mx1 = rmax4(mx1);
        const float mn0 = fmaxf(mrow0, mx0), mn1 = fmaxf(mrow1, mx1);
        const float c0 = ex2f(mrow0 - mn0), c1 = ex2f(mrow1 - mn1);
        mrow0 = mn0; mrow1 = mn1;
        float s0 = 0.f, s1 = 0.f;
#pragma unroll
        for (int nt = 0; nt < 8; nt++) {
            sc[nt][0] = ex2f(sc[nt][0] - mn0); s0 += sc[nt][0];
            sc[nt][1] = ex2f(sc[nt][1] - mn0); s0 += sc[nt][1];
            sc[nt][2] = ex2f(sc[nt][2] - mn1); s1 += sc[nt][2];
            sc[nt][3] = ex2f(sc[nt][3] - mn1); s1 += sc[nt][3];
        }
        s0 = rsum4(s0); s1 = rsum4(s1);
        lrow0 = lrow0 * c0 + s0;
        lrow1 = lrow1 * c1 + s1;
#pragma unroll
        for (int nt = 0; nt < 8; nt++) {
            o[nt][0] *= c0; o[nt][1] *= c0;
            o[nt][2] *= c1; o[nt][3] *= c1;
        }

        // ---- P @ V, 1-term: P fp16 x V fp16 ----
#pragma unroll
        for (int kc = 0; kc < 4; kc++) {
            uint32_t ph[4];
            ph[0] = packh2(sc[2 * kc][0],     sc[2 * kc][1]);
            ph[1] = packh2(sc[2 * kc][2],     sc[2 * kc][3]);
            ph[2] = packh2(sc[2 * kc + 1][0], sc[2 * kc + 1][1]);
            ph[3] = packh2(sc[2 * kc + 1][2], sc[2 * kc + 1][3]);
#pragma unroll
            for (int gp = 0; gp < 2; gp++) {
                uint32_t vh[2][4];
#pragma unroll
                for (int gi = 0; gi < 2; gi++) {
                    const int g = gp * 2 + gi;
                    const uint32_t ad = stg + 2 * AT_TILEB
                        + (uint32_t)(g * 16 + (lane & 7) + ((lane >> 4) << 3)) * AT_ROWB
                        + kc * 32 + (((lane >> 3) & 1) << 4);
                    ldsm4(vh[gi][0], vh[gi][1], vh[gi][2], vh[gi][3], ad);
                }
#pragma unroll
                for (int gi = 0; gi < 2; gi++) {
                    const int g = gp * 2 + gi;
                    mma16816(o[2 * g],     ph, &vh[gi][0]);
                    mma16816(o[2 * g + 1], ph, &vh[gi][2]);
                }
            }
        }
    }

    // ---- epilogue: normalize, write fp16 only ----
    const float i0 = 1.f / lrow0, i1 = 1.f / lrow1;
    const int r0 = qwb + (lane >> 2);
    const int dbase = 2 * (lane & 3);
#pragma unroll
    for (int nt = 0; nt < 8; nt++) {
        const int d = nt * 8 + dbase;
        size_t base = ((size_t)head * SEQ + r0) * DK + d;
        *(uint32_t*)&g_Ah[base] = packh2(o[nt][0] * i0, o[nt][1] * i0);
        base = ((size_t)head * SEQ + r0 + 8) * DK + d;
        *(uint32_t*)&g_Ah[base] = packh2(o[nt][2] * i1, o[nt][3] * i1);
    }
}

// =================================================================
extern "C" void kernel_launch(void* const* d_in, const int* in_sizes, int n_in,
                              void* d_out, int out_size)
{
    const float* X  = (const float*)d_in[0];
    const float* Wq = (const float*)d_in[1];
    const float* Wk = (const float*)d_in[2];
    const float* Wv = (const float*)d_in[3];
    const float* Wo = (const float*)d_in[4];
    float* out = (float*)d_out;

    cudaFuncSetAttribute(gemm_qkv_mma, cudaFuncAttributeMaxDynamicSharedMemorySize, GEMM_SMEM);
    cudaFuncSetAttribute(gemm_out_mma, cudaFuncAttributeMaxDynamicSharedMemorySize, GEMM_SMEM);
    cudaFuncSetAttribute(attn_mma,     cudaFuncAttributeMaxDynamicSharedMemorySize, ATTN_SMEM);

    cvt_all<<<8192, 256>>>(X, Wq, Wk, Wv, Wo);

    dim3 gProj(D_MODEL / BN, M_TOTAL / BM, 3);     // (8, 32, 3)
    gemm_qkv_mma<<<gProj, 256, GEMM_SMEM>>>();

    dim3 gAttn(SEQ / 128, HEADS_TOT);              // (16, 32)
    attn_mma<<<gAttn, 256, ATTN_SMEM>>>();

    dim3 gOut(D_MODEL / BN, M_TOTAL / BM);         // (8, 32)
    gemm_out_mma<<<gOut, 256, GEMM_SMEM>>>(out);
}

// round 15
// speedup vs baseline: 1.0111x; 1.0111x over previous
#include <cuda_runtime.h>
#include <cuda_fp16.h>
#include <cstdint>
#include <math.h>

#define D_MODEL   1024
#define NUM_HEADS 16
#define DK        64
#define BATCH     2
#define SEQ       2048
#define M_TOTAL   (BATCH * SEQ)          // 4096
#define HEADS_TOT (BATCH * NUM_HEADS)    // 32

// log2(e)/sqrt(64) folded into Q
#define QSCALE 0.18033688011112042f

// ---------------- scratch (no cudaMalloc allowed) ----------------
__device__ __half g_Xh[(size_t)M_TOTAL * D_MODEL];
__device__ __half g_Xl[(size_t)M_TOTAL * D_MODEL];
__device__ __half g_Wh[4][(size_t)D_MODEL * D_MODEL];
__device__ __half g_Wl[4][(size_t)D_MODEL * D_MODEL];
__device__ __half g_Qh[(size_t)HEADS_TOT * SEQ * DK];
__device__ __half g_Ql[(size_t)HEADS_TOT * SEQ * DK];
__device__ __half g_Kh[(size_t)HEADS_TOT * SEQ * DK];
__device__ __half g_Kl[(size_t)HEADS_TOT * SEQ * DK];
__device__ __half g_Vth[(size_t)HEADS_TOT * DK * SEQ];  // fp16-only V (transposed)
__device__ __half g_Ah[(size_t)HEADS_TOT * SEQ * DK];   // attn out, fp16 only

// ---------------- ptx helpers ----------------
__device__ __forceinline__ uint32_t smem_u32(const void* p) {
    uint32_t a;
    asm("{ .reg .u64 t; cvta.to.shared.u64 t, %1; cvt.u32.u64 %0, t; }" : "=r"(a) : "l"(p));
    return a;
}
__device__ __forceinline__ void cp16(uint32_t dst, const void* src) {
    asm volatile("cp.async.cg.shared.global [%0], [%1], 16;" :: "r"(dst), "l"(src));
}
#define CP_COMMIT() asm volatile("cp.async.commit_group;" ::: "memory")
#define CP_WAIT(n)  asm volatile("cp.async.wait_group %0;" :: "n"(n) : "memory")

__device__ __forceinline__ void ldsm4(uint32_t& r0, uint32_t& r1, uint32_t& r2, uint32_t& r3,
                                      uint32_t addr) {
    asm volatile("ldmatrix.sync.aligned.m8n8.x4.shared.b16 {%0,%1,%2,%3}, [%4];"
                 : "=r"(r0), "=r"(r1), "=r"(r2), "=r"(r3) : "r"(addr));
}
__device__ __forceinline__ void mma16816(float* d, const uint32_t* a, const uint32_t* b) {
    asm volatile("mma.sync.aligned.m16n8k16.row.col.f32.f16.f16.f32 "
        "{%0,%1,%2,%3}, {%4,%5,%6,%7}, {%8,%9}, {%0,%1,%2,%3};"
        : "+f"(d[0]), "+f"(d[1]), "+f"(d[2]), "+f"(d[3])
        : "r"(a[0]), "r"(a[1]), "r"(a[2]), "r"(a[3]), "r"(b[0]), "r"(b[1]));
}
__device__ __forceinline__ void splith2(float x, float y, uint32_t& hi, uint32_t& lo) {
    __half2 H = __floats2half2_rn(x, y);
    float rx = x - __half2float(__low2half(H));
    float ry = y - __half2float(__high2half(H));
    __half2 L = __floats2half2_rn(rx, ry);
    hi = *(uint32_t*)&H;
    lo = *(uint32_t*)&L;
}
__device__ __forceinline__ uint32_t packh2(float x, float y) {
    __half2 H = __floats2half2_rn(x, y);
    return *(uint32_t*)&H;
}
__device__ __forceinline__ float ex2f(float x) {
    float r; asm("ex2.approx.f32 %0, %1;" : "=f"(r) : "f"(x)); return r;
}
__device__ __forceinline__ float rmax4(float v) {
    v = fmaxf(v, __shfl_xor_sync(0xffffffffu, v, 1));
    v = fmaxf(v, __shfl_xor_sync(0xffffffffu, v, 2));
    return v;
}
__device__ __forceinline__ float rsum4(float v) {
    v += __shfl_xor_sync(0xffffffffu, v, 1);
    v += __shfl_xor_sync(0xffffffffu, v, 2);
    return v;
}

// =================================================================
// fused fp32 -> (hi, lo) fp16 split for X + 4 weights (one launch)
// (lo skipped for Wv/Wo — value path is fp16-only now)
// =================================================================
__global__ __launch_bounds__(256)
void cvt_all(const float* __restrict__ X,  const float* __restrict__ Wq,
             const float* __restrict__ Wk, const float* __restrict__ Wv,
             const float* __restrict__ Wo)
{
    const int bid = blockIdx.x;
    const float* src;
    __half *hi, *lo;
    bool wlo = true;
    int i;
    if (bid < 4096) {
        src = X; hi = g_Xh; lo = g_Xl;
        i = bid * 256 + threadIdx.x;
    } else {
        const int seg = (bid - 4096) >> 10;
        i = ((bid - 4096) & 1023) * 256 + threadIdx.x;
        src = seg == 0 ? Wq : seg == 1 ? Wk : seg == 2 ? Wv : Wo;
        hi = g_Wh[seg]; lo = g_Wl[seg];
        wlo = (seg < 2);
    }
    float4 v = ((const float4*)src)[i];
    uint32_t h0, l0, h1, l1;
    splith2(v.x, v.y, h0, l0);
    splith2(v.z, v.w, h1, l1);
    ((uint2*)hi)[i] = make_uint2(h0, h1);
    if (wlo) ((uint2*)lo)[i] = make_uint2(l0, l1);
}

// =================================================================
// split-fp16 HMMA GEMM: block 128x128, BK=32, 8 warps (4x2), warp 32x64.
// terms = 3 (hh+hl+lh), 2 (hh+hl), or 1 (hh). f32 acc.
// =================================================================
#define BM 128
#define BN 128
#define BK 32
#define SSTR   40
#define TILE_B (BM * SSTR * 2)
#define STAGE_B (4 * TILE_B)
#define GEMM_SMEM (2 * STAGE_B)          // 81920 B

template<bool QKV>
__device__ __forceinline__ void issue_copies(uint32_t stage_sb, int tid, int m0, int n0, int kc,
                                             const __half* __restrict__ Wh,
                                             const __half* __restrict__ Wl,
                                             bool copy_alo, bool copy_blo)
{
    const int k0 = kc * BK;
#pragma unroll
    for (int o = 0; o < 8; o++) {
        const int e    = o * 256 + tid;
        const int tile = e >> 9;
        if (tile == 1 && !copy_alo) continue;
        if (tile == 3 && !copy_blo) continue;
        const int idx  = e & 511;
        const int r = idx >> 2, c = idx & 3;
        const uint32_t dst = stage_sb + tile * TILE_B + r * (SSTR * 2) + c * 16;
        const __half* src;
        if (tile < 2) {
            size_t ai;
            if (QKV) {
                ai = (size_t)(m0 + r) * D_MODEL + k0 + c * 8;
            } else {
                const int m = m0 + r;
                ai = (((size_t)(m >> 11) * NUM_HEADS + (k0 >> 6)) * SEQ + (m & (SEQ - 1))) * DK
                     + (k0 & 63) + c * 8;
            }
            src = (tile == 0 ? (QKV ? g_Xh : g_Ah) : g_Xl) + ai;
        } else {
            const size_t bi = (size_t)(n0 + r) * D_MODEL + k0 + c * 8;
            src = (tile == 2 ? Wh : Wl) + bi;
        }
        cp16(dst, src);
    }
}

__device__ __forceinline__ void mma_stage(uint32_t Abase, int lane, int wm, int wn,
                                          float acc[2][8][4], int terms)
{
#pragma unroll
    for (int h = 0; h < 2; h++) {
        uint32_t ah[2][4], al[2][4];
#pragma unroll
        for (int mt = 0; mt < 2; mt++) {
            const uint32_t addr = Abase
                + (uint32_t)(wm * 32 + mt * 16 + (lane & 15)) * (SSTR * 2)
                + h * 32 + ((lane >> 4) << 4);
            ldsm4(ah[mt][0], ah[mt][1], ah[mt][2], ah[mt][3], addr);
            if (terms >= 3)
                ldsm4(al[mt][0], al[mt][1], al[mt][2], al[mt][3], addr + TILE_B);
        }
        uint32_t bh[4][4], bl[4][4];
#pragma unroll
        for (int nt = 0; nt < 4; nt++) {
            const uint32_t addr = Abase + 2 * TILE_B
                + (uint32_t)(wn * 64 + nt * 16 + (lane & 7) + ((lane >> 4) << 3)) * (SSTR * 2)
                + h * 32 + (((lane >> 3) & 1) << 4);
            ldsm4(bh[nt][0], bh[nt][1], bh[nt][2], bh[nt][3], addr);
            if (terms >= 2)
                ldsm4(bl[nt][0], bl[nt][1], bl[nt][2], bl[nt][3], addr + TILE_B);
        }
#pragma unroll
        for (int mt = 0; mt < 2; mt++)
#pragma unroll
            for (int nt = 0; nt < 4; nt++) {
                mma16816(acc[mt][2 * nt],     ah[mt], &bh[nt][0]);
                mma16816(acc[mt][2 * nt + 1], ah[mt], &bh[nt][2]);
            }
        if (terms >= 2) {
#pragma unroll
            for (int mt = 0; mt < 2; mt++)
#pragma unroll
                for (int nt = 0; nt < 4; nt++) {
                    mma16816(acc[mt][2 * nt],     ah[mt], &bl[nt][0]);
                    mma16816(acc[mt][2 * nt + 1], ah[mt], &bl[nt][2]);
                }
        }
        if (terms >= 3) {
#pragma unroll
            for (int mt = 0; mt < 2; mt++)
#pragma unroll
                for (int nt = 0; nt < 4; nt++) {
                    mma16816(acc[mt][2 * nt],     al[mt], &bh[nt][0]);
                    mma16816(acc[mt][2 * nt + 1], al[mt], &bh[nt][2]);
                }
        }
    }
}

template<bool QKV>
__device__ __forceinline__ void gemm_body(float acc[2][8][4], uint32_t sb, int tid,
                                          int m0, int n0, int terms,
                                          const __half* __restrict__ Wh,
                                          const __half* __restrict__ Wl)
{
    const int lane = tid & 31, wid = tid >> 5;
    const int wm = wid >> 1, wn = wid & 1;
    const int NKC = D_MODEL / BK;
    const bool ca = (terms >= 3), cb = (terms >= 2);

    issue_copies<QKV>(sb, tid, m0, n0, 0, Wh, Wl, ca, cb);
    CP_COMMIT();
    for (int kc = 0; kc < NKC; kc++) {
        CP_WAIT(0);
        __syncthreads();
        if (kc + 1 < NKC) {
            issue_copies<QKV>(sb + ((kc + 1) & 1) * STAGE_B, tid, m0, n0, kc + 1, Wh, Wl, ca, cb);
            CP_COMMIT();
        }
        mma_stage(sb + (kc & 1) * STAGE_B, lane, wm, wn, acc, terms);
    }
}

__global__ __launch_bounds__(256, 2)
void gemm_qkv_mma()
{
    extern __shared__ char smem[];
    const uint32_t sb = smem_u32(smem);
    const int tid = threadIdx.x;
    const int z  = blockIdx.z;
    const int m0 = blockIdx.y * BM, n0 = blockIdx.x * BN;

    float acc[2][8][4];
#pragma unroll
    for (int a = 0; a < 2; a++)
#pragma unroll
        for (int b = 0; b < 8; b++)
#pragma unroll
            for (int c = 0; c < 4; c++) acc[a][b][c] = 0.f;

    // Q,K: 3-term (score path). V: 1-term (value path, fp16 x fp16).
    gemm_body<true>(acc, sb, tid, m0, n0, (z < 2) ? 3 : 1, g_Wh[z], g_Wl[z]);

    const float scale = (z == 0) ? QSCALE : 1.0f;
    const int lane = tid & 31, wid = tid >> 5;
    const int wm = wid >> 1, wn = wid & 1;
    const int h = ((n0 + wn * 64) >> 6);
#pragma unroll
    for (int mt = 0; mt < 2; mt++)
#pragma unroll
        for (int rr = 0; rr < 2; rr++) {
            const int m = m0 + wm * 32 + mt * 16 + rr * 8 + (lane >> 2);
            const int b = m >> 11, s = m & (SEQ - 1);
            const int head = b * NUM_HEADS + h;
#pragma unroll
            for (int j = 0; j < 8; j++) {
                const int t = j * 8 + 2 * (lane & 3);
                const float x = acc[mt][j][2 * rr] * scale;
                const float y = acc[mt][j][2 * rr + 1] * scale;
                if (z == 2) {
                    const size_t base = ((size_t)head * DK + t) * SEQ + s;
                    g_Vth[base]       = __float2half_rn(x);
                    g_Vth[base + SEQ] = __float2half_rn(y);
                } else {
                    uint32_t hi, lo;
                    splith2(x, y, hi, lo);
                    const size_t base = ((size_t)head * SEQ + s) * DK + t;
                    if (z == 0) {
                        *(uint32_t*)&g_Qh[base] = hi;
                        *(uint32_t*)&g_Ql[base] = lo;
                    } else {
                        *(uint32_t*)&g_Kh[base] = hi;
                        *(uint32_t*)&g_Kl[base] = lo;
                    }
                }
            }
        }
}

__global__ __launch_bounds__(256, 2)
void gemm_out_mma(float* __restrict__ C)
{
    extern __shared__ char smem[];
    const uint32_t sb = smem_u32(smem);
    const int tid = threadIdx.x;
    const int m0 = blockIdx.y * BM, n0 = blockIdx.x * BN;

    float acc[2][8][4];
#pragma unroll
    for (int a = 0; a < 2; a++)
#pragma unroll
        for (int b = 0; b < 8; b++)
#pragma unroll
            for (int c = 0; c < 4; c++) acc[a][b][c] = 0.f;

    // value path: 1-term (A = attn out fp16, B = Wo fp16)
    gemm_body<false>(acc, sb, tid, m0, n0, 1, g_Wh[3], g_Wl[3]);

    const int lane = tid & 31, wid = tid >> 5;
    const int wm = wid >> 1, wn = wid & 1;
#pragma unroll
    for (int mt = 0; mt < 2; mt++)
#pragma unroll
        for (int rr = 0; rr < 2; rr++) {
            const int m = m0 + wm * 32 + mt * 16 + rr * 8 + (lane >> 2);
            float* dst = &C[(size_t)m * D_MODEL + n0 + wn * 64];
#pragma unroll
            for (int j = 0; j < 8; j++) {
                const int t = j * 8 + 2 * (lane & 3);
                float2 v = rr == 0 ? make_float2(acc[mt][j][0], acc[mt][j][1])
                                   : make_float2(acc[mt][j][2], acc[mt][j][3]);
                *(float2*)&dst[t] = v;
            }
        }
}

// =================================================================
// Flash attention: QK 3-term (22-bit scores), PV 1-term (fp16 x fp16).
// Stage = {Kh, Kl, Vth} = 3 tiles. Double-buffered, causal warp skip.
// =================================================================
#define AT_SSTR  72
#define AT_ROWB  (AT_SSTR * 2)           // 144
#define AT_TILEB (64 * AT_ROWB)          // 9216
#define AT_STAGE (3 * AT_TILEB)          // 27648
#define ATTN_SMEM (2 * AT_STAGE)         // 55296

__device__ __forceinline__ void attn_issue(uint32_t stage_sb, int tid, int head, int k0)
{
#pragma unroll
    for (int i = 0; i < 6; i++) {
        const int e = i * 256 + tid;                 // 0..1535
        const int arr = e >> 9, idx = e & 511;
        const int row = idx >> 3, c = idx & 7;
        const uint32_t dst = stage_sb + arr * AT_TILEB + row * AT_ROWB + c * 16;
        const __half* src;
        if (arr == 0)      src = g_Kh  + ((size_t)head * SEQ + k0 + row) * DK + c * 8;
        else if (arr == 1) src = g_Kl  + ((size_t)head * SEQ + k0 + row) * DK + c * 8;
        else               src = g_Vth + ((size_t)head * DK + row) * SEQ + k0 + c * 8;
        cp16(dst, src);
    }
}

__global__ __launch_bounds__(256)
void attn_mma()
{
    extern __shared__ char smem[];
    const uint32_t sb = smem_u32(smem);
    const int tid = threadIdx.x, lane = tid & 31, w = tid >> 5;
    const int head = blockIdx.y;
    const int q0 = (int)(gridDim.x - 1 - blockIdx.x) * 128;
    const int qwb = q0 + w * 16;

    // ---- stage Q (hi = tiles 0-1, lo = tiles 2-3 of smem area) ----
    {
        const __half* Qh = g_Qh + ((size_t)head * SEQ + q0) * DK;
        const __half* Ql = g_Ql + ((size_t)head * SEQ + q0) * DK;
#pragma unroll
        for (int i = 0; i < 8; i++) {
            const int e = i * 256 + tid;
            const int half_ = e >> 10;
            const int idx = e & 1023;
            const int row = idx >> 3, c = idx & 7;
            const uint32_t dst = sb + half_ * (2 * AT_TILEB) + row * AT_ROWB + c * 16;
            const __half* src = (half_ ? Ql : Qh) + (size_t)row * DK + c * 8;
            cp16(dst, src);
        }
        CP_COMMIT(); CP_WAIT(0);
        __syncthreads();
    }
    uint32_t qh[4][4], ql[4][4];
#pragma unroll
    for (int kc = 0; kc < 4; kc++) {
        const uint32_t a = sb + (uint32_t)(w * 16 + (lane & 15)) * AT_ROWB
                         + kc * 32 + ((lane >> 4) << 4);
        ldsm4(qh[kc][0], qh[kc][1], qh[kc][2], qh[kc][3], a);
        ldsm4(ql[kc][0], ql[kc][1], ql[kc][2], ql[kc][3], a + 2 * AT_TILEB);
    }
    __syncthreads();

    float o[8][4];
#pragma unroll
    for (int nt = 0; nt < 8; nt++)
#pragma unroll
        for (int r = 0; r < 4; r++) o[nt][r] = 0.f;
    float mrow0 = -1e30f, mrow1 = -1e30f, lrow0 = 0.f, lrow1 = 0.f;

    const int ktiles = (q0 >> 6) + 2;

    attn_issue(sb, tid, head, 0);
    CP_COMMIT();

    for (int t = 0; t < ktiles; t++) {
        const int k0 = t * 64;
        CP_WAIT(0);
        __syncthreads();
        if (t + 1 < ktiles) {
            attn_issue(sb + ((t + 1) & 1) * AT_STAGE, tid, head, k0 + 64);
            CP_COMMIT();
        }
        if (k0 > qwb + 15) continue;           // fully-masked tile for this warp
        const uint32_t stg = sb + (t & 1) * AT_STAGE;

        // ---- QK^T, 3-term (score path) ----
        float sc[8][4];
#pragma unroll
        for (int nt = 0; nt < 8; nt++)
#pragma unroll
            for (int r = 0; r < 4; r++) sc[nt][r] = 0.f;
#pragma unroll
        for (int kc = 0; kc < 4; kc++)
#pragma unroll
            for (int gp = 0; gp < 2; gp++) {
                uint32_t kh[2][4], kl[2][4];
#pragma unroll
                for (int gi = 0; gi < 2; gi++) {
                    const int g = gp * 2 + gi;
                    const uint32_t ad = stg
                        + (uint32_t)(g * 16 + (lane & 7) + ((lane >> 4) << 3)) * AT_ROWB
                        + kc * 32 + (((lane >> 3) & 1) << 4);
                    ldsm4(kh[gi][0], kh[gi][1], kh[gi][2], kh[gi][3], ad);
                    ldsm4(kl[gi][0], kl[gi][1], kl[gi][2], kl[gi][3], ad + AT_TILEB);
                }
#pragma unroll
                for (int gi = 0; gi < 2; gi++) {
                    const int g = gp * 2 + gi;
                    mma16816(sc[2 * g],     qh[kc], &kh[gi][0]);
                    mma16816(sc[2 * g + 1], qh[kc], &kh[gi][2]);
                }
#pragma unroll
                for (int gi = 0; gi < 2; gi++) {
                    const int g = gp * 2 + gi;
                    mma16816(sc[2 * g],     qh[kc], &kl[gi][0]);
                    mma16816(sc[2 * g + 1], qh[kc], &kl[gi][2]);
                }
#pragma unroll
                for (int gi = 0; gi < 2; gi++) {
                    const int g = gp * 2 + gi;
                    mma16816(sc[2 * g],     ql[kc], &kh[gi][0]);
                    mma16816(sc[2 * g + 1], ql[kc], &kh[gi][2]);
                }
            }

        // ---- causal mask (diagonal tiles only) ----
        if (k0 + 63 > qwb) {
            const int r0 = qwb + (lane >> 2);
            const int kb = k0 + 2 * (lane & 3);
#pragma unroll
            for (int nt = 0; nt < 8; nt++) {
                const int kk = kb + nt * 8;
                if (kk     > r0)     sc[nt][0] = -1e30f;
                if (kk + 1 > r0)     sc[nt][1] = -1e30f;
                if (kk     > r0 + 8) sc[nt][2] = -1e30f;
                if (kk + 1 > r0 + 8) sc[nt][3] = -1e30f;
            }
        }

        // ---- online softmax (base 2) ----
        float mx0 = sc[0][0], mx1 = sc[0][2];
#pragma unroll
        for (int nt = 0; nt < 8; nt++) {
            mx0 = fmaxf(mx0, fmaxf(sc[nt][0], sc[nt][1]));
            mx1 = fmaxf(mx1, fmaxf(sc[nt][2], sc[nt][3]));
        }
        mx0 = rmax4(mx0); mx1 = rmax4(mx1);
        const float mn0 = fmaxf(mrow0, mx0), mn1 = fmaxf(mrow1, mx1);
        const float c0 = ex2f(mrow0 - mn0), c1 = ex2f(mrow1 - mn1);
        mrow0 = mn0; mrow1 = mn1;
        float s0 = 0.f, s1 = 0.f;
#pragma unroll
        for (int nt = 0; nt < 8; nt++) {
            sc[nt][0] = ex2f(sc[nt][0] - mn0); s0 += sc[nt][0];
            sc[nt][1] = ex2f(sc[nt][1] - mn0); s0 += sc[nt][1];
            sc[nt][2] = ex2f(sc[nt][2] - mn1); s1 += sc[nt][2];
            sc[nt][3] = ex2f(sc[nt][3] - mn1); s1 += sc[nt][3];
        }
        s0 = rsum4(s0); s1 = rsum4(s1);
        lrow0 = lrow0 * c0 + s0;
        lrow1 = lrow1 * c1 + s1;
#pragma unroll
        for (int nt = 0; nt < 8; nt++) {
            o[nt][0] *= c0; o[nt][1] *= c0;
            o[nt][2] *= c1; o[nt][3] *= c1;
        }

        // ---- P @ V, 1-term: P fp16 x V fp16 ----
#pragma unroll
        for (int kc = 0; kc < 4; kc++) {
            uint32_t ph[4];
            ph[0] = packh2(sc[2 * kc][0],     sc[2 * kc][1]);
            ph[1] = packh2(sc[2 * kc][2],     sc[2 * kc][3]);
            ph[2] = packh2(sc[2 * kc + 1][0], sc[2 * kc + 1][1]);
            ph[3] = packh2(sc[2 * kc + 1][2], sc[2 * kc + 1][3]);
#pragma unroll
            for (int gp = 0; gp < 2; gp++) {
                uint32_t vh[2][4];
#pragma unroll
                for (int gi = 0; gi < 2; gi++) {
                    const int g = gp * 2 + gi;
                    const uint32_t ad = stg + 2 * AT_TILEB
                        + (uint32_t)(g * 16 + (lane & 7) + ((lane >> 4) << 3)) * AT_ROWB
                        + kc * 32 + (((lane >> 3) & 1) << 4);
                    ldsm4(vh[gi][0], vh[gi][1], vh[gi][2], vh[gi][3], ad);
                }
#pragma unroll
                for (int gi = 0; gi < 2; gi++) {
                    const int g = gp * 2 + gi;
                    mma16816(o[2 * g],     ph, &vh[gi][0]);
                    mma16816(o[2 * g + 1], ph, &vh[gi][2]);
                }
            }
        }
    }

    // ---- epilogue: normalize, write fp16 only ----
    const float i0 = 1.f / lrow0, i1 = 1.f / lrow1;
    const int r0 = qwb + (lane >> 2);
    const int dbase = 2 * (lane & 3);
#pragma unroll
    for (int nt = 0; nt < 8; nt++) {
        const int d = nt * 8 + dbase;
        size_t base = ((size_t)head * SEQ + r0) * DK + d;
        *(uint32_t*)&g_Ah[base] = packh2(o[nt][0] * i0, o[nt][1] * i0);
        base = ((size_t)head * SEQ + r0 + 8) * DK + d;
        *(uint32_t*)&g_Ah[base] = packh2(o[nt][2] * i1, o[nt][3] * i1);
    }
}

// =================================================================
extern "C" void kernel_launch(void* const* d_in, const int* in_sizes, int n_in,
                              void* d_out, int out_size)
{
    const float* X  = (const float*)d_in[0];
    const float* Wq = (const float*)d_in[1];
    const float* Wk = (const float*)d_in[2];
    const float* Wv = (const float*)d_in[3];
    const float* Wo = (const float*)d_in[4];
    float* out = (float*)d_out;

    cudaFuncSetAttribute(gemm_qkv_mma, cudaFuncAttributeMaxDynamicSharedMemorySize, GEMM_SMEM);
    cudaFuncSetAttribute(gemm_out_mma, cudaFuncAttributeMaxDynamicSharedMemorySize, GEMM_SMEM);
    cudaFuncSetAttribute(attn_mma,     cudaFuncAttributeMaxDynamicSharedMemorySize, ATTN_SMEM);

    cvt_all<<<8192, 256>>>(X, Wq, Wk, Wv, Wo);

    dim3 gProj(D_MODEL / BN, M_TOTAL / BM, 3);     // (8, 32, 3)
    gemm_qkv_mma<<<gProj, 256, GEMM_SMEM>>>();

    dim3 gAttn(SEQ / 128, HEADS_TOT);              // (16, 32)
    attn_mma<<<gAttn, 256, ATTN_SMEM>>>();

    dim3 gOut(D_MODEL / BN, M_TOTAL / BM);         // (8, 32)
    gemm_out_mma<<<gOut, 256, GEMM_SMEM>>>(out);
}

// round 16
// speedup vs baseline: 1.2121x; 1.1988x over previous
#include <cuda_runtime.h>
#include <cuda_fp16.h>
#include <cstdint>
#include <math.h>

#define D_MODEL   1024
#define NUM_HEADS 16
#define DK        64
#define BATCH     2
#define SEQ       2048
#define M_TOTAL   (BATCH * SEQ)          // 4096
#define HEADS_TOT (BATCH * NUM_HEADS)    // 32

// log2(e)/sqrt(64) folded into Q
#define QSCALE 0.18033688011112042f

// ---------------- scratch (no cudaMalloc allowed) ----------------
__device__ __half g_Xh[(size_t)M_TOTAL * D_MODEL];
__device__ __half g_Xl[(size_t)M_TOTAL * D_MODEL];   // unused at runtime (kept for template refs)
__device__ __half g_Wh[4][(size_t)D_MODEL * D_MODEL];
__device__ __half g_Wl[4][(size_t)D_MODEL * D_MODEL];
__device__ __half g_Qh[(size_t)HEADS_TOT * SEQ * DK];  // Q, fp16 only
__device__ __half g_Kh[(size_t)HEADS_TOT * SEQ * DK];
__device__ __half g_Kl[(size_t)HEADS_TOT * SEQ * DK];
__device__ __half g_Vth[(size_t)HEADS_TOT * DK * SEQ];  // fp16-only V (transposed)
__device__ __half g_Ah[(size_t)HEADS_TOT * SEQ * DK];   // attn out, fp16 only

// ---------------- ptx helpers ----------------
__device__ __forceinline__ uint32_t smem_u32(const void* p) {
    uint32_t a;
    asm("{ .reg .u64 t; cvta.to.shared.u64 t, %1; cvt.u32.u64 %0, t; }" : "=r"(a) : "l"(p));
    return a;
}
__device__ __forceinline__ void cp16(uint32_t dst, const void* src) {
    asm volatile("cp.async.cg.shared.global [%0], [%1], 16;" :: "r"(dst), "l"(src));
}
#define CP_COMMIT() asm volatile("cp.async.commit_group;" ::: "memory")
#define CP_WAIT(n)  asm volatile("cp.async.wait_group %0;" :: "n"(n) : "memory")

__device__ __forceinline__ void ldsm4(uint32_t& r0, uint32_t& r1, uint32_t& r2, uint32_t& r3,
                                      uint32_t addr) {
    asm volatile("ldmatrix.sync.aligned.m8n8.x4.shared.b16 {%0,%1,%2,%3}, [%4];"
                 : "=r"(r0), "=r"(r1), "=r"(r2), "=r"(r3) : "r"(addr));
}
__device__ __forceinline__ void mma16816(float* d, const uint32_t* a, const uint32_t* b) {
    asm volatile("mma.sync.aligned.m16n8k16.row.col.f32.f16.f16.f32 "
        "{%0,%1,%2,%3}, {%4,%5,%6,%7}, {%8,%9}, {%0,%1,%2,%3};"
        : "+f"(d[0]), "+f"(d[1]), "+f"(d[2]), "+f"(d[3])
        : "r"(a[0]), "r"(a[1]), "r"(a[2]), "r"(a[3]), "r"(b[0]), "r"(b[1]));
}
__device__ __forceinline__ void splith2(float x, float y, uint32_t& hi, uint32_t& lo) {
    __half2 H = __floats2half2_rn(x, y);
    float rx = x - __half2float(__low2half(H));
    float ry = y - __half2float(__high2half(H));
    __half2 L = __floats2half2_rn(rx, ry);
    hi = *(uint32_t*)&H;
    lo = *(uint32_t*)&L;
}
__device__ __forceinline__ uint32_t packh2(float x, float y) {
    __half2 H = __floats2half2_rn(x, y);
    return *(uint32_t*)&H;
}
__device__ __forceinline__ float ex2f(float x) {
    float r; asm("ex2.approx.f32 %0, %1;" : "=f"(r) : "f"(x)); return r;
}
__device__ __forceinline__ float rmax4(float v) {
    v = fmaxf(v, __shfl_xor_sync(0xffffffffu, v, 1));
    v = fmaxf(v, __shfl_xor_sync(0xffffffffu, v, 2));
    return v;
}
__device__ __forceinline__ float rsum4(float v) {
    v += __shfl_xor_sync(0xffffffffu, v, 1);
    v += __shfl_xor_sync(0xffffffffu, v, 2);
    return v;
}

// =================================================================
// fused fp32 -> fp16 (hi, +lo for Wq/Wk) conversion, one launch
// X: hi only. Wq, Wk: hi+lo. Wv, Wo: hi only.
// =================================================================
__global__ __launch_bounds__(256)
void cvt_all(const float* __restrict__ X,  const float* __restrict__ Wq,
             const float* __restrict__ Wk, const float* __restrict__ Wv,
             const float* __restrict__ Wo)
{
    const int bid = blockIdx.x;
    const float* src;
    __half *hi, *lo = nullptr;
    bool wlo = false;
    int i;
    if (bid < 4096) {
        src = X; hi = g_Xh;
        i = bid * 256 + threadIdx.x;
    } else {
        const int seg = (bid - 4096) >> 10;
        i = ((bid - 4096) & 1023) * 256 + threadIdx.x;
        src = seg == 0 ? Wq : seg == 1 ? Wk : seg == 2 ? Wv : Wo;
        hi = g_Wh[seg]; lo = g_Wl[seg];
        wlo = (seg < 2);
    }
    float4 v = ((const float4*)src)[i];
    uint32_t h0, l0, h1, l1;
    splith2(v.x, v.y, h0, l0);
    splith2(v.z, v.w, h1, l1);
    ((uint2*)hi)[i] = make_uint2(h0, h1);
    if (wlo) ((uint2*)lo)[i] = make_uint2(l0, l1);
}

// =================================================================
// split-fp16 HMMA GEMM: block 128x128, BK=32, 8 warps (4x2), warp 32x64.
// terms = 2 (A-hi x {B-hi, B-lo}) or 1 (A-hi x B-hi). f32 acc.
// =================================================================
#define BM 128
#define BN 128
#define BK 32
#define SSTR   40
#define TILE_B (BM * SSTR * 2)
#define STAGE_B (4 * TILE_B)
#define GEMM_SMEM (2 * STAGE_B)          // 81920 B

template<bool QKV>
__device__ __forceinline__ void issue_copies(uint32_t stage_sb, int tid, int m0, int n0, int kc,
                                             const __half* __restrict__ Wh,
                                             const __half* __restrict__ Wl,
                                             bool copy_blo)
{
    const int k0 = kc * BK;
#pragma unroll
    for (int o = 0; o < 8; o++) {
        const int e    = o * 256 + tid;
        const int tile = e >> 9;
        if (tile == 1) continue;                        // A-lo never used
        if (tile == 3 && !copy_blo) continue;
        const int idx  = e & 511;
        const int r = idx >> 2, c = idx & 3;
        const uint32_t dst = stage_sb + tile * TILE_B + r * (SSTR * 2) + c * 16;
        const __half* src;
        if (tile < 2) {
            size_t ai;
            if (QKV) {
                ai = (size_t)(m0 + r) * D_MODEL + k0 + c * 8;
            } else {
                const int m = m0 + r;
                ai = (((size_t)(m >> 11) * NUM_HEADS + (k0 >> 6)) * SEQ + (m & (SEQ - 1))) * DK
                     + (k0 & 63) + c * 8;
            }
            src = (QKV ? g_Xh : g_Ah) + ai;
        } else {
            const size_t bi = (size_t)(n0 + r) * D_MODEL + k0 + c * 8;
            src = (tile == 2 ? Wh : Wl) + bi;
        }
        cp16(dst, src);
    }
}

__device__ __forceinline__ void mma_stage(uint32_t Abase, int lane, int wm, int wn,
                                          float acc[2][8][4], int terms)
{
#pragma unroll
    for (int h = 0; h < 2; h++) {
        uint32_t ah[2][4];
#pragma unroll
        for (int mt = 0; mt < 2; mt++) {
            const uint32_t addr = Abase
                + (uint32_t)(wm * 32 + mt * 16 + (lane & 15)) * (SSTR * 2)
                + h * 32 + ((lane >> 4) << 4);
            ldsm4(ah[mt][0], ah[mt][1], ah[mt][2], ah[mt][3], addr);
        }
        uint32_t bh[4][4], bl[4][4];
#pragma unroll
        for (int nt = 0; nt < 4; nt++) {
            const uint32_t addr = Abase + 2 * TILE_B
                + (uint32_t)(wn * 64 + nt * 16 + (lane & 7) + ((lane >> 4) << 3)) * (SSTR * 2)
                + h * 32 + (((lane >> 3) & 1) << 4);
            ldsm4(bh[nt][0], bh[nt][1], bh[nt][2], bh[nt][3], addr);
            if (terms >= 2)
                ldsm4(bl[nt][0], bl[nt][1], bl[nt][2], bl[nt][3], addr + TILE_B);
        }
#pragma unroll
        for (int mt = 0; mt < 2; mt++)
#pragma unroll
            for (int nt = 0; nt < 4; nt++) {
                mma16816(acc[mt][2 * nt],     ah[mt], &bh[nt][0]);
                mma16816(acc[mt][2 * nt + 1], ah[mt], &bh[nt][2]);
            }
        if (terms >= 2) {
#pragma unroll
            for (int mt = 0; mt < 2; mt++)
#pragma unroll
                for (int nt = 0; nt < 4; nt++) {
                    mma16816(acc[mt][2 * nt],     ah[mt], &bl[nt][0]);
                    mma16816(acc[mt][2 * nt + 1], ah[mt], &bl[nt][2]);
                }
        }
    }
}

template<bool QKV>
__device__ __forceinline__ void gemm_body(float acc[2][8][4], uint32_t sb, int tid,
                                          int m0, int n0, int terms,
                                          const __half* __restrict__ Wh,
                                          const __half* __restrict__ Wl)
{
    const int lane = tid & 31, wid = tid >> 5;
    const int wm = wid >> 1, wn = wid & 1;
    const int NKC = D_MODEL / BK;
    const bool cb = (terms >= 2);

    issue_copies<QKV>(sb, tid, m0, n0, 0, Wh, Wl, cb);
    CP_COMMIT();
    for (int kc = 0; kc < NKC; kc++) {
        CP_WAIT(0);
        __syncthreads();
        if (kc + 1 < NKC) {
            issue_copies<QKV>(sb + ((kc + 1) & 1) * STAGE_B, tid, m0, n0, kc + 1, Wh, Wl, cb);
            CP_COMMIT();
        }
        mma_stage(sb + (kc & 1) * STAGE_B, lane, wm, wn, acc, terms);
    }
}

__global__ __launch_bounds__(256, 2)
void gemm_qkv_mma()
{
    extern __shared__ char smem[];
    const uint32_t sb = smem_u32(smem);
    const int tid = threadIdx.x;
    const int z  = blockIdx.z;
    const int m0 = blockIdx.y * BM, n0 = blockIdx.x * BN;

    float acc[2][8][4];
#pragma unroll
    for (int a = 0; a < 2; a++)
#pragma unroll
        for (int b = 0; b < 8; b++)
#pragma unroll
            for (int c = 0; c < 4; c++) acc[a][b][c] = 0.f;

    // Q,K: 2-term (A = Xh, B = W split). V: 1-term.
    gemm_body<true>(acc, sb, tid, m0, n0, (z < 2) ? 2 : 1, g_Wh[z], g_Wl[z]);

    const float scale = (z == 0) ? QSCALE : 1.0f;
    const int lane = tid & 31, wid = tid >> 5;
    const int wm = wid >> 1, wn = wid & 1;
    const int h = ((n0 + wn * 64) >> 6);
#pragma unroll
    for (int mt = 0; mt < 2; mt++)
#pragma unroll
        for (int rr = 0; rr < 2; rr++) {
            const int m = m0 + wm * 32 + mt * 16 + rr * 8 + (lane >> 2);
            const int b = m >> 11, s = m & (SEQ - 1);
            const int head = b * NUM_HEADS + h;
#pragma unroll
            for (int j = 0; j < 8; j++) {
                const int t = j * 8 + 2 * (lane & 3);
                const float x = acc[mt][j][2 * rr] * scale;
                const float y = acc[mt][j][2 * rr + 1] * scale;
                if (z == 2) {
                    const size_t base = ((size_t)head * DK + t) * SEQ + s;
                    g_Vth[base]       = __float2half_rn(x);
                    g_Vth[base + SEQ] = __float2half_rn(y);
                } else if (z == 0) {
                    // Q: fp16 only
                    const size_t base = ((size_t)head * SEQ + s) * DK + t;
                    *(uint32_t*)&g_Qh[base] = packh2(x, y);
                } else {
                    // K: split hi/lo
                    uint32_t hi, lo;
                    splith2(x, y, hi, lo);
                    const size_t base = ((size_t)head * SEQ + s) * DK + t;
                    *(uint32_t*)&g_Kh[base] = hi;
                    *(uint32_t*)&g_Kl[base] = lo;
                }
            }
        }
}

__global__ __launch_bounds__(256, 2)
void gemm_out_mma(float* __restrict__ C)
{
    extern __shared__ char smem[];
    const uint32_t sb = smem_u32(smem);
    const int tid = threadIdx.x;
    const int m0 = blockIdx.y * BM, n0 = blockIdx.x * BN;

    float acc[2][8][4];
#pragma unroll
    for (int a = 0; a < 2; a++)
#pragma unroll
        for (int b = 0; b < 8; b++)
#pragma unroll
            for (int c = 0; c < 4; c++) acc[a][b][c] = 0.f;

    // value path: 1-term (A = attn out fp16, B = Wo fp16)
    gemm_body<false>(acc, sb, tid, m0, n0, 1, g_Wh[3], g_Wl[3]);

    const int lane = tid & 31, wid = tid >> 5;
    const int wm = wid >> 1, wn = wid & 1;
#pragma unroll
    for (int mt = 0; mt < 2; mt++)
#pragma unroll
        for (int rr = 0; rr < 2; rr++) {
            const int m = m0 + wm * 32 + mt * 16 + rr * 8 + (lane >> 2);
            float* dst = &C[(size_t)m * D_MODEL + n0 + wn * 64];
#pragma unroll
            for (int j = 0; j < 8; j++) {
                const int t = j * 8 + 2 * (lane & 3);
                float2 v = rr == 0 ? make_float2(acc[mt][j][0], acc[mt][j][1])
                                   : make_float2(acc[mt][j][2], acc[mt][j][3]);
                *(float2*)&dst[t] = v;
            }
        }
}

// =================================================================
// Flash attention: QK 2-term (qh x {kh, kl}), PV 1-term.
// Stage = {Kh, Kl, Vth} = 3 tiles. Double-buffered, causal warp skip.
// =================================================================
#define AT_SSTR  72
#define AT_ROWB  (AT_SSTR * 2)           // 144
#define AT_TILEB (64 * AT_ROWB)          // 9216
#define AT_STAGE (3 * AT_TILEB)          // 27648
#define ATTN_SMEM (2 * AT_STAGE)         // 55296

__device__ __forceinline__ void attn_issue(uint32_t stage_sb, int tid, int head, int k0)
{
#pragma unroll
    for (int i = 0; i < 6; i++) {
        const int e = i * 256 + tid;                 // 0..1535
        const int arr = e >> 9, idx = e & 511;
        const int row = idx >> 3, c = idx & 7;
        const uint32_t dst = stage_sb + arr * AT_TILEB + row * AT_ROWB + c * 16;
        const __half* src;
        if (arr == 0)      src = g_Kh  + ((size_t)head * SEQ + k0 + row) * DK + c * 8;
        else if (arr == 1) src = g_Kl  + ((size_t)head * SEQ + k0 + row) * DK + c * 8;
        else               src = g_Vth + ((size_t)head * DK + row) * SEQ + k0 + c * 8;
        cp16(dst, src);
    }
}

__global__ __launch_bounds__(256)
void attn_mma()
{
    extern __shared__ char smem[];
    const uint32_t sb = smem_u32(smem);
    const int tid = threadIdx.x, lane = tid & 31, w = tid >> 5;
    const int head = blockIdx.y;
    const int q0 = (int)(gridDim.x - 1 - blockIdx.x) * 128;
    const int qwb = q0 + w * 16;

    // ---- stage Q-hi (tiles 0-1), load A frags ----
    {
        const __half* Qh = g_Qh + ((size_t)head * SEQ + q0) * DK;
#pragma unroll
        for (int i = 0; i < 4; i++) {
            const int e = i * 256 + tid;           // 0..1023
            const int row = e >> 3, c = e & 7;
            const uint32_t dst = sb + row * AT_ROWB + c * 16;
            cp16(dst, Qh + (size_t)row * DK + c * 8);
        }
        CP_COMMIT(); CP_WAIT(0);
        __syncthreads();
    }
    uint32_t qh[4][4];
#pragma unroll
    for (int kc = 0; kc < 4; kc++) {
        const uint32_t a = sb + (uint32_t)(w * 16 + (lane & 15)) * AT_ROWB
                         + kc * 32 + ((lane >> 4) << 4);
        ldsm4(qh[kc][0], qh[kc][1], qh[kc][2], qh[kc][3], a);
    }
    __syncthreads();

    float o[8][4];
#pragma unroll
    for (int nt = 0; nt < 8; nt++)
#pragma unroll
        for (int r = 0; r < 4; r++) o[nt][r] = 0.f;
    float mrow0 = -1e30f, mrow1 = -1e30f, lrow0 = 0.f, lrow1 = 0.f;

    const int ktiles = (q0 >> 6) + 2;

    attn_issue(sb, tid, head, 0);
    CP_COMMIT();

    for (int t = 0; t < ktiles; t++) {
        const int k0 = t * 64;
        CP_WAIT(0);
        __syncthreads();
        if (t + 1 < ktiles) {
            attn_issue(sb + ((t + 1) & 1) * AT_STAGE, tid, head, k0 + 64);
            CP_COMMIT();
        }
        if (k0 > qwb + 15) continue;           // fully-masked tile for this warp
        const uint32_t stg = sb + (t & 1) * AT_STAGE;

        // ---- QK^T, 2-term: qh·kh + qh·kl ----
        float sc[8][4];
#pragma unroll
        for (int nt = 0; nt < 8; nt++)
#pragma unroll
            for (int r = 0; r < 4; r++) sc[nt][r] = 0.f;
#pragma unroll
        for (int kc = 0; kc < 4; kc++)
#pragma unroll
            for (int gp = 0; gp < 2; gp++) {
                uint32_t kh[2][4], kl[2][4];
#pragma unroll
                for (int gi = 0; gi < 2; gi++) {
                    const int g = gp * 2 + gi;
                    const uint32_t ad = stg
                        + (uint32_t)(g * 16 + (lane & 7) + ((lane >> 4) << 3)) * AT_ROWB
                        + kc * 32 + (((lane >> 3) & 1) << 4);
                    ldsm4(kh[gi][0], kh[gi][1], kh[gi][2], kh[gi][3], ad);
                    ldsm4(kl[gi][0], kl[gi][1], kl[gi][2], kl[gi][3], ad + AT_TILEB);
                }
#pragma unroll
                for (int gi = 0; gi < 2; gi++) {
                    const int g = gp * 2 + gi;
                    mma16816(sc[2 * g],     qh[kc], &kh[gi][0]);
                    mma16816(sc[2 * g + 1], qh[kc], &kh[gi][2]);
                }
#pragma unroll
                for (int gi = 0; gi < 2; gi++) {
                    const int g = gp * 2 + gi;
                    mma16816(sc[2 * g],     qh[kc], &kl[gi][0]);
                    mma16816(sc[2 * g + 1], qh[kc], &kl[gi][2]);
                }
            }

        // ---- causal mask (diagonal tiles only) ----
        if (k0 + 63 > qwb) {
            const int r0 = qwb + (lane >> 2);
            const int kb = k0 + 2 * (lane & 3);
#pragma unroll
            for (int nt = 0; nt < 8; nt++) {
                const int kk = kb + nt * 8;
                if (kk     > r0)     sc[nt][0] = -1e30f;
                if (kk + 1 > r0)     sc[nt][1] = -1e30f;
                if (kk     > r0 + 8) sc[nt][2] = -1e30f;
                if (kk + 1 > r0 + 8) sc[nt][3] = -1e30f;
            }
        }

        // ---- online softmax (base 2) ----
        float mx0 = sc[0][0], mx1 = sc[0][2];
#pragma unroll
        for (int nt = 0; nt < 8; nt++) {
            mx0 = fmaxf(mx0, fmaxf(sc[nt][0], sc[nt][1]));
            mx1 = fmaxf(mx1, fmaxf(sc[nt][2], sc[nt][3]));
        }
        mx0 = rmax4(mx0); mx1 = rmax4(mx1);
        const float mn0 = fmaxf(mrow0, mx0), mn1 = fmaxf(mrow1, mx1);
        const float c0 = ex2f(mrow0 - mn0), c1 = ex2f(mrow1 - mn1);
        mrow0 = mn0; mrow1 = mn1;
        float s0 = 0.f, s1 = 0.f;
#pragma unroll
        for (int nt = 0; nt < 8; nt++) {
            sc[nt][0] = ex2f(sc[nt][0] - mn0); s0 += sc[nt][0];
            sc[nt][1] = ex2f(sc[nt][1] - mn0); s0 += sc[nt][1];
            sc[nt][2] = ex2f(sc[nt][2] - mn1); s1 += sc[nt][2];
            sc[nt][3] = ex2f(sc[nt][3] - mn1); s1 += sc[nt][3];
        }
        s0 = rsum4(s0); s1 = rsum4(s1);
        lrow0 = lrow0 * c0 + s0;
        lrow1 = lrow1 * c1 + s1;
#pragma unroll
        for (int nt = 0; nt < 8; nt++) {
            o[nt][0] *= c0; o[nt][1] *= c0;
            o[nt][2] *= c1; o[nt][3] *= c1;
        }

        // ---- P @ V, 1-term: P fp16 x V fp16 ----
#pragma unroll
        for (int kc = 0; kc < 4; kc++) {
            uint32_t ph[4];
            ph[0] = packh2(sc[2 * kc][0],     sc[2 * kc][1]);
            ph[1] = packh2(sc[2 * kc][2],     sc[2 * kc][3]);
            ph[2] = packh2(sc[2 * kc + 1][0], sc[2 * kc + 1][1]);
            ph[3] = packh2(sc[2 * kc + 1][2], sc[2 * kc + 1][3]);
#pragma unroll
            for (int gp = 0; gp < 2; gp++) {
                uint32_t vh[2][4];
#pragma unroll
                for (int gi = 0; gi < 2; gi++) {
                    const int g = gp * 2 + gi;
                    const uint32_t ad = stg + 2 * AT_TILEB
                        + (uint32_t)(g * 16 + (lane & 7) + ((lane >> 4) << 3)) * AT_ROWB
                        + kc * 32 + (((lane >> 3) & 1) << 4);
                    ldsm4(vh[gi][0], vh[gi][1], vh[gi][2], vh[gi][3], ad);
                }
#pragma unroll
                for (int gi = 0; gi < 2; gi++) {
                    const int g = gp * 2 + gi;
                    mma16816(o[2 * g],     ph, &vh[gi][0]);
                    mma16816(o[2 * g + 1], ph, &vh[gi][2]);
                }
            }
        }
    }

    // ---- epilogue: normalize, write fp16 only ----
    const float i0 = 1.f / lrow0, i1 = 1.f / lrow1;
    const int r0 = qwb + (lane >> 2);
    const int dbase = 2 * (lane & 3);
#pragma unroll
    for (int nt = 0; nt < 8; nt++) {
        const int d = nt * 8 + dbase;
        size_t base = ((size_t)head * SEQ + r0) * DK + d;
        *(uint32_t*)&g_Ah[base] = packh2(o[nt][0] * i0, o[nt][1] * i0);
        base = ((size_t)head * SEQ + r0 + 8) * DK + d;
        *(uint32_t*)&g_Ah[base] = packh2(o[nt][2] * i1, o[nt][3] * i1);
    }
}

// =================================================================
extern "C" void kernel_launch(void* const* d_in, const int* in_sizes, int n_in,
                              void* d_out, int out_size)
{
    const float* X  = (const float*)d_in[0];
    const float* Wq = (const float*)d_in[1];
    const float* Wk = (const float*)d_in[2];
    const float* Wv = (const float*)d_in[3];
    const float* Wo = (const float*)d_in[4];
    float* out = (float*)d_out;

    cudaFuncSetAttribute(gemm_qkv_mma, cudaFuncAttributeMaxDynamicSharedMemorySize, GEMM_SMEM);
    cudaFuncSetAttribute(gemm_out_mma, cudaFuncAttributeMaxDynamicSharedMemorySize, GEMM_SMEM);
    cudaFuncSetAttribute(attn_mma,     cudaFuncAttributeMaxDynamicSharedMemorySize, ATTN_SMEM);

    cvt_all<<<8192, 256>>>(X, Wq, Wk, Wv, Wo);

    dim3 gProj(D_MODEL / BN, M_TOTAL / BM, 3);     // (8, 32, 3)
    gemm_qkv_mma<<<gProj, 256, GEMM_SMEM>>>();

    dim3 gAttn(SEQ / 128, HEADS_TOT);              // (16, 32)
    attn_mma<<<gAttn, 256, ATTN_SMEM>>>();

    dim3 gOut(D_MODEL / BN, M_TOTAL / BM);         // (8, 32)
    gemm_out_mma<<<gOut, 256, GEMM_SMEM>>>(out);
}

// round 17
// speedup vs baseline: 1.3384x; 1.1042x over previous
#include <cuda_runtime.h>
#include <cuda_fp16.h>
#include <cstdint>
#include <math.h>

#define D_MODEL   1024
#define NUM_HEADS 16
#define DK        64
#define BATCH     2
#define SEQ       2048
#define M_TOTAL   (BATCH * SEQ)          // 4096
#define HEADS_TOT (BATCH * NUM_HEADS)    // 32

// log2(e)/sqrt(64) folded into Q
#define QSCALE 0.18033688011112042f

// ---------------- scratch (no cudaMalloc allowed) ----------------
__device__ __half g_Xh[(size_t)M_TOTAL * D_MODEL];
__device__ __half g_Wh[4][(size_t)D_MODEL * D_MODEL];
__device__ __half g_Wl[4][(size_t)D_MODEL * D_MODEL];   // used for Wq, Wk only
__device__ __half g_Qh[(size_t)HEADS_TOT * SEQ * DK];   // Q, fp16 only
__device__ __half g_Kh[(size_t)HEADS_TOT * SEQ * DK];   // K, fp16 only
__device__ __half g_Vth[(size_t)HEADS_TOT * DK * SEQ];  // V transposed, fp16
__device__ __half g_Ah[(size_t)HEADS_TOT * SEQ * DK];   // attn out, fp16

// ---------------- ptx helpers ----------------
__device__ __forceinline__ uint32_t smem_u32(const void* p) {
    uint32_t a;
    asm("{ .reg .u64 t; cvta.to.shared.u64 t, %1; cvt.u32.u64 %0, t; }" : "=r"(a) : "l"(p));
    return a;
}
__device__ __forceinline__ void cp16(uint32_t dst, const void* src) {
    asm volatile("cp.async.cg.shared.global [%0], [%1], 16;" :: "r"(dst), "l"(src));
}
#define CP_COMMIT() asm volatile("cp.async.commit_group;" ::: "memory")
#define CP_WAIT(n)  asm volatile("cp.async.wait_group %0;" :: "n"(n) : "memory")

__device__ __forceinline__ void ldsm4(uint32_t& r0, uint32_t& r1, uint32_t& r2, uint32_t& r3,
                                      uint32_t addr) {
    asm volatile("ldmatrix.sync.aligned.m8n8.x4.shared.b16 {%0,%1,%2,%3}, [%4];"
                 : "=r"(r0), "=r"(r1), "=r"(r2), "=r"(r3) : "r"(addr));
}
__device__ __forceinline__ void mma16816(float* d, const uint32_t* a, const uint32_t* b) {
    asm volatile("mma.sync.aligned.m16n8k16.row.col.f32.f16.f16.f32 "
        "{%0,%1,%2,%3}, {%4,%5,%6,%7}, {%8,%9}, {%0,%1,%2,%3};"
        : "+f"(d[0]), "+f"(d[1]), "+f"(d[2]), "+f"(d[3])
        : "r"(a[0]), "r"(a[1]), "r"(a[2]), "r"(a[3]), "r"(b[0]), "r"(b[1]));
}
__device__ __forceinline__ void splith2(float x, float y, uint32_t& hi, uint32_t& lo) {
    __half2 H = __floats2half2_rn(x, y);
    float rx = x - __half2float(__low2half(H));
    float ry = y - __half2float(__high2half(H));
    __half2 L = __floats2half2_rn(rx, ry);
    hi = *(uint32_t*)&H;
    lo = *(uint32_t*)&L;
}
__device__ __forceinline__ uint32_t packh2(float x, float y) {
    __half2 H = __floats2half2_rn(x, y);
    return *(uint32_t*)&H;
}
__device__ __forceinline__ float ex2f(float x) {
    float r; asm("ex2.approx.f32 %0, %1;" : "=f"(r) : "f"(x)); return r;
}
__device__ __forceinline__ float rmax4(float v) {
    v = fmaxf(v, __shfl_xor_sync(0xffffffffu, v, 1));
    v = fmaxf(v, __shfl_xor_sync(0xffffffffu, v, 2));
    return v;
}
__device__ __forceinline__ float rsum4(float v) {
    v += __shfl_xor_sync(0xffffffffu, v, 1);
    v += __shfl_xor_sync(0xffffffffu, v, 2);
    return v;
}

// =================================================================
// fused fp32 -> fp16 (hi, +lo for Wq/Wk) conversion, one launch
// =================================================================
__global__ __launch_bounds__(256)
void cvt_all(const float* __restrict__ X,  const float* __restrict__ Wq,
             const float* __restrict__ Wk, const float* __restrict__ Wv,
             const float* __restrict__ Wo)
{
    const int bid = blockIdx.x;
    const float* src;
    __half *hi, *lo = nullptr;
    bool wlo = false;
    int i;
    if (bid < 4096) {
        src = X; hi = g_Xh;
        i = bid * 256 + threadIdx.x;
    } else {
        const int seg = (bid - 4096) >> 10;
        i = ((bid - 4096) & 1023) * 256 + threadIdx.x;
        src = seg == 0 ? Wq : seg == 1 ? Wk : seg == 2 ? Wv : Wo;
        hi = g_Wh[seg]; lo = g_Wl[seg];
        wlo = (seg < 2);
    }
    float4 v = ((const float4*)src)[i];
    uint32_t h0, l0, h1, l1;
    splith2(v.x, v.y, h0, l0);
    splith2(v.z, v.w, h1, l1);
    ((uint2*)hi)[i] = make_uint2(h0, h1);
    if (wlo) ((uint2*)lo)[i] = make_uint2(l0, l1);
}

// =================================================================
// split-fp16 HMMA GEMM: block 128x128, BK=32, 8 warps (4x2), warp 32x64.
// terms = 2 (A-hi x {B-hi, B-lo}) or 1 (A-hi x B-hi). f32 acc.
// =================================================================
#define BM 128
#define BN 128
#define BK 32
#define SSTR   40
#define TILE_B (BM * SSTR * 2)
#define STAGE_B (4 * TILE_B)
#define GEMM_SMEM (2 * STAGE_B)          // 81920 B

template<bool QKV>
__device__ __forceinline__ void issue_copies(uint32_t stage_sb, int tid, int m0, int n0, int kc,
                                             const __half* __restrict__ Wh,
                                             const __half* __restrict__ Wl,
                                             bool copy_blo)
{
    const int k0 = kc * BK;
#pragma unroll
    for (int o = 0; o < 8; o++) {
        const int e    = o * 256 + tid;
        const int tile = e >> 9;
        if (tile == 1) continue;                        // A-lo never used
        if (tile == 3 && !copy_blo) continue;
        const int idx  = e & 511;
        const int r = idx >> 2, c = idx & 3;
        const uint32_t dst = stage_sb + tile * TILE_B + r * (SSTR * 2) + c * 16;
        const __half* src;
        if (tile < 2) {
            size_t ai;
            if (QKV) {
                ai = (size_t)(m0 + r) * D_MODEL + k0 + c * 8;
            } else {
                const int m = m0 + r;
                ai = (((size_t)(m >> 11) * NUM_HEADS + (k0 >> 6)) * SEQ + (m & (SEQ - 1))) * DK
                     + (k0 & 63) + c * 8;
            }
            src = (QKV ? g_Xh : g_Ah) + ai;
        } else {
            const size_t bi = (size_t)(n0 + r) * D_MODEL + k0 + c * 8;
            src = (tile == 2 ? Wh : Wl) + bi;
        }
        cp16(dst, src);
    }
}

__device__ __forceinline__ void mma_stage(uint32_t Abase, int lane, int wm, int wn,
                                          float acc[2][8][4], int terms)
{
#pragma unroll
    for (int h = 0; h < 2; h++) {
        uint32_t ah[2][4];
#pragma unroll
        for (int mt = 0; mt < 2; mt++) {
            const uint32_t addr = Abase
                + (uint32_t)(wm * 32 + mt * 16 + (lane & 15)) * (SSTR * 2)
                + h * 32 + ((lane >> 4) << 4);
            ldsm4(ah[mt][0], ah[mt][1], ah[mt][2], ah[mt][3], addr);
        }
        uint32_t bh[4][4], bl[4][4];
#pragma unroll
        for (int nt = 0; nt < 4; nt++) {
            const uint32_t addr = Abase + 2 * TILE_B
                + (uint32_t)(wn * 64 + nt * 16 + (lane & 7) + ((lane >> 4) << 3)) * (SSTR * 2)
                + h * 32 + (((lane >> 3) & 1) << 4);
            ldsm4(bh[nt][0], bh[nt][1], bh[nt][2], bh[nt][3], addr);
            if (terms >= 2)
                ldsm4(bl[nt][0], bl[nt][1], bl[nt][2], bl[nt][3], addr + TILE_B);
        }
#pragma unroll
        for (int mt = 0; mt < 2; mt++)
#pragma unroll
            for (int nt = 0; nt < 4; nt++) {
                mma16816(acc[mt][2 * nt],     ah[mt], &bh[nt][0]);
                mma16816(acc[mt][2 * nt + 1], ah[mt], &bh[nt][2]);
            }
        if (terms >= 2) {
#pragma unroll
            for (int mt = 0; mt < 2; mt++)
#pragma unroll
                for (int nt = 0; nt < 4; nt++) {
                    mma16816(acc[mt][2 * nt],     ah[mt], &bl[nt][0]);
                    mma16816(acc[mt][2 * nt + 1], ah[mt], &bl[nt][2]);
                }
        }
    }
}

template<bool QKV>
__device__ __forceinline__ void gemm_body(float acc[2][8][4], uint32_t sb, int tid,
                                          int m0, int n0, int terms,
                                          const __half* __restrict__ Wh,
                                          const __half* __restrict__ Wl)
{
    const int lane = tid & 31, wid = tid >> 5;
    const int wm = wid >> 1, wn = wid & 1;
    const int NKC = D_MODEL / BK;
    const bool cb = (terms >= 2);

    issue_copies<QKV>(sb, tid, m0, n0, 0, Wh, Wl, cb);
    CP_COMMIT();
    for (int kc = 0; kc < NKC; kc++) {
        CP_WAIT(0);
        __syncthreads();
        if (kc + 1 < NKC) {
            issue_copies<QKV>(sb + ((kc + 1) & 1) * STAGE_B, tid, m0, n0, kc + 1, Wh, Wl, cb);
            CP_COMMIT();
        }
        mma_stage(sb + (kc & 1) * STAGE_B, lane, wm, wn, acc, terms);
    }
}

__global__ __launch_bounds__(256, 2)
void gemm_qkv_mma()
{
    extern __shared__ char smem[];
    const uint32_t sb = smem_u32(smem);
    const int tid = threadIdx.x;
    const int z  = blockIdx.z;
    const int m0 = blockIdx.y * BM, n0 = blockIdx.x * BN;

    float acc[2][8][4];
#pragma unroll
    for (int a = 0; a < 2; a++)
#pragma unroll
        for (int b = 0; b < 8; b++)
#pragma unroll
            for (int c = 0; c < 4; c++) acc[a][b][c] = 0.f;

    // Q,K: 2-term (A = Xh, B = W split). V: 1-term.
    gemm_body<true>(acc, sb, tid, m0, n0, (z < 2) ? 2 : 1, g_Wh[z], g_Wl[z]);

    const float scale = (z == 0) ? QSCALE : 1.0f;
    const int lane = tid & 31, wid = tid >> 5;
    const int wm = wid >> 1, wn = wid & 1;
    const int h = ((n0 + wn * 64) >> 6);
#pragma unroll
    for (int mt = 0; mt < 2; mt++)
#pragma unroll
        for (int rr = 0; rr < 2; rr++) {
            const int m = m0 + wm * 32 + mt * 16 + rr * 8 + (lane >> 2);
            const int b = m >> 11, s = m & (SEQ - 1);
            const int head = b * NUM_HEADS + h;
#pragma unroll
            for (int j = 0; j < 8; j++) {
                const int t = j * 8 + 2 * (lane & 3);
                const float x = acc[mt][j][2 * rr] * scale;
                const float y = acc[mt][j][2 * rr + 1] * scale;
                if (z == 2) {
                    const size_t base = ((size_t)head * DK + t) * SEQ + s;
                    g_Vth[base]       = __float2half_rn(x);
                    g_Vth[base + SEQ] = __float2half_rn(y);
                } else {
                    // Q and K: fp16 only
                    const size_t base = ((size_t)head * SEQ + s) * DK + t;
                    __half* dst = (z == 0) ? g_Qh : g_Kh;
                    *(uint32_t*)&dst[base] = packh2(x, y);
                }
            }
        }
}

__global__ __launch_bounds__(256, 2)
void gemm_out_mma(float* __restrict__ C)
{
    extern __shared__ char smem[];
    const uint32_t sb = smem_u32(smem);
    const int tid = threadIdx.x;
    const int m0 = blockIdx.y * BM, n0 = blockIdx.x * BN;

    float acc[2][8][4];
#pragma unroll
    for (int a = 0; a < 2; a++)
#pragma unroll
        for (int b = 0; b < 8; b++)
#pragma unroll
            for (int c = 0; c < 4; c++) acc[a][b][c] = 0.f;

    // value path: 1-term (A = attn out fp16, B = Wo fp16)
    gemm_body<false>(acc, sb, tid, m0, n0, 1, g_Wh[3], g_Wl[3]);

    const int lane = tid & 31, wid = tid >> 5;
    const int wm = wid >> 1, wn = wid & 1;
#pragma unroll
    for (int mt = 0; mt < 2; mt++)
#pragma unroll
        for (int rr = 0; rr < 2; rr++) {
            const int m = m0 + wm * 32 + mt * 16 + rr * 8 + (lane >> 2);
            float* dst = &C[(size_t)m * D_MODEL + n0 + wn * 64];
#pragma unroll
            for (int j = 0; j < 8; j++) {
                const int t = j * 8 + 2 * (lane & 3);
                float2 v = rr == 0 ? make_float2(acc[mt][j][0], acc[mt][j][1])
                                   : make_float2(acc[mt][j][2], acc[mt][j][3]);
                *(float2*)&dst[t] = v;
            }
        }
}

// =================================================================
// Flash attention: QK 1-term (qh x kh), PV 1-term.
// Stage = {Kh, Vth} = 2 tiles. Double-buffered, causal warp skip.
// =================================================================
#define AT_SSTR  72
#define AT_ROWB  (AT_SSTR * 2)           // 144
#define AT_TILEB (64 * AT_ROWB)          // 9216
#define AT_STAGE (2 * AT_TILEB)          // 18432
#define ATTN_SMEM (2 * AT_STAGE)         // 36864

__device__ __forceinline__ void attn_issue(uint32_t stage_sb, int tid, int head, int k0)
{
#pragma unroll
    for (int i = 0; i < 4; i++) {
        const int e = i * 256 + tid;                 // 0..1023
        const int arr = e >> 9, idx = e & 511;       // 0 = Kh, 1 = Vth
        const int row = idx >> 3, c = idx & 7;
        const uint32_t dst = stage_sb + arr * AT_TILEB + row * AT_ROWB + c * 16;
        const __half* src;
        if (arr == 0) src = g_Kh  + ((size_t)head * SEQ + k0 + row) * DK + c * 8;
        else          src = g_Vth + ((size_t)head * DK + row) * SEQ + k0 + c * 8;
        cp16(dst, src);
    }
}

__global__ __launch_bounds__(256)
void attn_mma()
{
    extern __shared__ char smem[];
    const uint32_t sb = smem_u32(smem);
    const int tid = threadIdx.x, lane = tid & 31, w = tid >> 5;
    const int head = blockIdx.y;
    const int q0 = (int)(gridDim.x - 1 - blockIdx.x) * 128;
    const int qwb = q0 + w * 16;

    // ---- stage Q-hi (fills stage 0 exactly), load A frags ----
    {
        const __half* Qh = g_Qh + ((size_t)head * SEQ + q0) * DK;
#pragma unroll
        for (int i = 0; i < 4; i++) {
            const int e = i * 256 + tid;           // 0..1023
            const int row = e >> 3, c = e & 7;
            const uint32_t dst = sb + row * AT_ROWB + c * 16;
            cp16(dst, Qh + (size_t)row * DK + c * 8);
        }
        CP_COMMIT(); CP_WAIT(0);
        __syncthreads();
    }
    uint32_t qh[4][4];
#pragma unroll
    for (int kc = 0; kc < 4; kc++) {
        const uint32_t a = sb + (uint32_t)(w * 16 + (lane & 15)) * AT_ROWB
                         + kc * 32 + ((lane >> 4) << 4);
        ldsm4(qh[kc][0], qh[kc][1], qh[kc][2], qh[kc][3], a);
    }
    __syncthreads();

    float o[8][4];
#pragma unroll
    for (int nt = 0; nt < 8; nt++)
#pragma unroll
        for (int r = 0; r < 4; r++) o[nt][r] = 0.f;
    float mrow0 = -1e30f, mrow1 = -1e30f, lrow0 = 0.f, lrow1 = 0.f;

    const int ktiles = (q0 >> 6) + 2;

    attn_issue(sb, tid, head, 0);
    CP_COMMIT();

    for (int t = 0; t < ktiles; t++) {
        const int k0 = t * 64;
        CP_WAIT(0);
        __syncthreads();
        if (t + 1 < ktiles) {
            attn_issue(sb + ((t + 1) & 1) * AT_STAGE, tid, head, k0 + 64);
            CP_COMMIT();
        }
        if (k0 > qwb + 15) continue;           // fully-masked tile for this warp
        const uint32_t stg = sb + (t & 1) * AT_STAGE;

        // ---- QK^T, 1-term: qh x kh ----
        float sc[8][4];
#pragma unroll
        for (int nt = 0; nt < 8; nt++)
#pragma unroll
            for (int r = 0; r < 4; r++) sc[nt][r] = 0.f;
#pragma unroll
        for (int kc = 0; kc < 4; kc++)
#pragma unroll
            for (int gp = 0; gp < 2; gp++) {
                uint32_t kh[2][4];
#pragma unroll
                for (int gi = 0; gi < 2; gi++) {
                    const int g = gp * 2 + gi;
                    const uint32_t ad = stg
                        + (uint32_t)(g * 16 + (lane & 7) + ((lane >> 4) << 3)) * AT_ROWB
                        + kc * 32 + (((lane >> 3) & 1) << 4);
                    ldsm4(kh[gi][0], kh[gi][1], kh[gi][2], kh[gi][3], ad);
                }
#pragma unroll
                for (int gi = 0; gi < 2; gi++) {
                    const int g = gp * 2 + gi;
                    mma16816(sc[2 * g],     qh[kc], &kh[gi][0]);
                    mma16816(sc[2 * g + 1], qh[kc], &kh[gi][2]);
                }
            }

        // ---- causal mask (diagonal tiles only) ----
        if (k0 + 63 > qwb) {
            const int r0 = qwb + (lane >> 2);
            const int kb = k0 + 2 * (lane & 3);
#pragma unroll
            for (int nt = 0; nt < 8; nt++) {
                const int kk = kb + nt * 8;
                if (kk     > r0)     sc[nt][0] = -1e30f;
                if (kk + 1 > r0)     sc[nt][1] = -1e30f;
                if (kk     > r0 + 8) sc[nt][2] = -1e30f;
                if (kk + 1 > r0 + 8) sc[nt][3] = -1e30f;
            }
        }

        // ---- online softmax (base 2) ----
        float mx0 = sc[0][0], mx1 = sc[0][2];
#pragma unroll
        for (int nt = 0; nt < 8; nt++) {
            mx0 = fmaxf(mx0, fmaxf(sc[nt][0], sc[nt][1]));
            mx1 = fmaxf(mx1, fmaxf(sc[nt][2], sc[nt][3]));
        }
        mx0 = rmax4(mx0); mx1 = rmax4(mx1);
        const float mn0 = fmaxf(mrow0, mx0), mn1 = fmaxf(mrow1, mx1);
        const float c0 = ex2f(mrow0 - mn0), c1 = ex2f(mrow1 - mn1);
        mrow0 = mn0; mrow1 = mn1;
        float s0 = 0.f, s1 = 0.f;
#pragma unroll
        for (int nt = 0; nt < 8; nt++) {
            sc[nt][0] = ex2f(sc[nt][0] - mn0); s0 += sc[nt][0];
            sc[nt][1] = ex2f(sc[nt][1] - mn0); s0 += sc[nt][1];
            sc[nt][2] = ex2f(sc[nt][2] - mn1); s1 += sc[nt][2];
            sc[nt][3] = ex2f(sc[nt][3] - mn1); s1 += sc[nt][3];
        }
        s0 = rsum4(s0); s1 = rsum4(s1);
        lrow0 = lrow0 * c0 + s0;
        lrow1 = lrow1 * c1 + s1;
#pragma unroll
        for (int nt = 0; nt < 8; nt++) {
            o[nt][0] *= c0; o[nt][1] *= c0;
            o[nt][2] *= c1; o[nt][3] *= c1;
        }

        // ---- P @ V, 1-term: P fp16 x V fp16 ----
#pragma unroll
        for (int kc = 0; kc < 4; kc++) {
            uint32_t ph[4];
            ph[0] = packh2(sc[2 * kc][0],     sc[2 * kc][1]);
            ph[1] = packh2(sc[2 * kc][2],     sc[2 * kc][3]);
            ph[2] = packh2(sc[2 * kc + 1][0], sc[2 * kc + 1][1]);
            ph[3] = packh2(sc[2 * kc + 1][2], sc[2 * kc + 1][3]);
#pragma unroll
            for (int gp = 0; gp < 2; gp++) {
                uint32_t vh[2][4];
#pragma unroll
                for (int gi = 0; gi < 2; gi++) {
                    const int g = gp * 2 + gi;
                    const uint32_t ad = stg + AT_TILEB
                        + (uint32_t)(g * 16 + (lane & 7) + ((lane >> 4) << 3)) * AT_ROWB
                        + kc * 32 + (((lane >> 3) & 1) << 4);
                    ldsm4(vh[gi][0], vh[gi][1], vh[gi][2], vh[gi][3], ad);
                }
#pragma unroll
                for (int gi = 0; gi < 2; gi++) {
                    const int g = gp * 2 + gi;
                    mma16816(o[2 * g],     ph, &vh[gi][0]);
                    mma16816(o[2 * g + 1], ph, &vh[gi][2]);
                }
            }
        }
    }

    // ---- epilogue: normalize, write fp16 only ----
    const float i0 = 1.f / lrow0, i1 = 1.f / lrow1;
    const int r0 = qwb + (lane >> 2);
    const int dbase = 2 * (lane & 3);
#pragma unroll
    for (int nt = 0; nt < 8; nt++) {
        const int d = nt * 8 + dbase;
        size_t base = ((size_t)head * SEQ + r0) * DK + d;
        *(uint32_t*)&g_Ah[base] = packh2(o[nt][0] * i0, o[nt][1] * i0);
        base = ((size_t)head * SEQ + r0 + 8) * DK + d;
        *(uint32_t*)&g_Ah[base] = packh2(o[nt][2] * i1, o[nt][3] * i1);
    }
}

// =================================================================
extern "C" void kernel_launch(void* const* d_in, const int* in_sizes, int n_in,
                              void* d_out, int out_size)
{
    const float* X  = (const float*)d_in[0];
    const float* Wq = (const float*)d_in[1];
    const float* Wk = (const float*)d_in[2];
    const float* Wv = (const float*)d_in[3];
    const float* Wo = (const float*)d_in[4];
    float* out = (float*)d_out;

    cudaFuncSetAttribute(gemm_qkv_mma, cudaFuncAttributeMaxDynamicSharedMemorySize, GEMM_SMEM);
    cudaFuncSetAttribute(gemm_out_mma, cudaFuncAttributeMaxDynamicSharedMemorySize, GEMM_SMEM);
    cudaFuncSetAttribute(attn_mma,     cudaFuncAttributeMaxDynamicSharedMemorySize, ATTN_SMEM);

    cvt_all<<<8192, 256>>>(X, Wq, Wk, Wv, Wo);

    dim3 gProj(D_MODEL / BN, M_TOTAL / BM, 3);     // (8, 32, 3)
    gemm_qkv_mma<<<gProj, 256, GEMM_SMEM>>>();

    dim3 gAttn(SEQ / 128, HEADS_TOT);              // (16, 32)
    attn_mma<<<gAttn, 256, ATTN_SMEM>>>();

    dim3 gOut(D_MODEL / BN, M_TOTAL / BM);         // (8, 32)
    gemm_out_mma<<<gOut, 256, GEMM_SMEM>>>(out);
}